// round 6
// baseline (speedup 1.0000x reference)
#include <cuda_runtime.h>
#include <cuda_bf16.h>
#include <mma.h>
#include <cstdint>

using namespace nvcuda;

#define BB 4
#define NN 4096
#define DIMV 128
#define DE 512
#define TOT (BB * NN)          // 16384 rows
#define CHUNK 16
#define NCHUNK (NN / CHUNK)    // 256

// Scratch (allocation-free: __device__ globals)
// g_sh per row: [0,512) = sigmoid(s) (gate), [512,1024) = gelu(h)
__device__ float g_sh[(size_t)TOT * 1024];
__device__ float g_o[(size_t)TOT * DE];      // gated aggregation, input to final GEMM
__device__ float g_part[BB * NCHUNK * DE];   // chunk partial sums -> exclusive offsets

#define BM 128
#define BKG 16
#define PAD 20                  // smem pitch (floats); 80B = mult of 16

__device__ __forceinline__ float gelu_exact(float x) {
    return 0.5f * x * (1.0f + erff(x * 0.70710678118654752f));
}
__device__ __forceinline__ float sigmoid_f(float x) {
    return 1.0f / (1.0f + expf(-x));
}

__device__ __forceinline__ void cp_async16(void* smem_dst, const void* gmem_src) {
    unsigned int s = (unsigned int)__cvta_generic_to_shared(smem_dst);
    asm volatile("cp.async.cg.shared.global [%0], [%1], 16;\n" :: "r"(s), "l"(gmem_src));
}
__device__ __forceinline__ void cp_commit() {
    asm volatile("cp.async.commit_group;\n");
}
template <int N>
__device__ __forceinline__ void cp_wait() {
    asm volatile("cp.async.wait_group %0;\n" :: "n"(N));
}

// ---------------------------------------------------------------------------
// tf32 wmma GEMM, BM=128 x BN tile, BK=16, 2-stage cp.async pipeline.
// 128 threads = 4 warps (2 M x 2 N); warp tile 64 x (BN/2).
//   out[m, j] = op( sum_k A[m,k] * W[j,k] + bias[j] )
// W row-major [Ntot, K]. Split weight at splitJ. op: 0=none 1=sigmoid 2=gelu
// ---------------------------------------------------------------------------
template <int BN>
__global__ __launch_bounds__(128) void gemm_tf32_kernel(
    const float* __restrict__ A, int lda,
    const float* __restrict__ W0, const float* __restrict__ bias0, int op0,
    const float* __restrict__ W1, const float* __restrict__ bias1, int op1,
    int splitJ, int K,
    float* __restrict__ out, int ldo)
{
    constexpr int NF = BN / 32;          // b-fragments per warp (4 for BN=128, 2 for BN=64)
    constexpr int STG = (BM + BN) * PAD; // floats per stage
    __shared__ float smem_all[2 * STG];  // <= 41 KB

    const int m0 = blockIdx.x * BM;
    const int j0 = blockIdx.y * BN;

    const float* W = W0;
    const float* bias = bias0;
    int op = op0;
    int jw = j0;
    if (j0 >= splitJ) { W = W1; bias = bias1; op = op1; jw = j0 - splitJ; }

    const int tid  = threadIdx.x;
    const int warp = tid >> 5;
    const int lane = tid & 31;
    const int wm = (warp & 1) * 64;        // warp row offset
    const int wn = (warp >> 1) * (BN / 2); // warp col offset

    const int niters = K / BKG;

    auto issue_load = [&](int it, int buf) {
        float* sa = smem_all + buf * STG;
        float* sb = sa + BM * PAD;
        int kb = it * BKG;
        // A: 128x16 = 512 float4 / 128 thr = 4 each
        #pragma unroll
        for (int i = 0; i < 4; i++) {
            int idx = tid + i * 128;
            int r  = idx >> 2;
            int c4 = (idx & 3) << 2;
            cp_async16(&sa[r * PAD + c4], &A[(size_t)(m0 + r) * lda + kb + c4]);
        }
        // B: BNx16 = BN*4 float4 / 128 thr
        #pragma unroll
        for (int i = 0; i < BN / 32; i++) {
            int idx = tid + i * 128;
            int r  = idx >> 2;
            int c4 = (idx & 3) << 2;
            cp_async16(&sb[r * PAD + c4], &W[(size_t)(jw + r) * K + kb + c4]);
        }
    };

    wmma::fragment<wmma::accumulator, 16, 16, 8, float> c[4][NF];
    #pragma unroll
    for (int i = 0; i < 4; i++)
        #pragma unroll
        for (int j = 0; j < NF; j++)
            wmma::fill_fragment(c[i][j], 0.0f);

    issue_load(0, 0);
    cp_commit();

    for (int it = 0; it < niters; it++) {
        if (it + 1 < niters) issue_load(it + 1, (it + 1) & 1);
        cp_commit();
        cp_wait<1>();          // newest (it+1) may remain pending; stage `it` ready
        __syncthreads();

        float* sa = smem_all + (it & 1) * STG;
        float* sb = sa + BM * PAD;

        #pragma unroll
        for (int kk = 0; kk < BKG; kk += 8) {
            wmma::fragment<wmma::matrix_a, 16, 16, 8, wmma::precision::tf32, wmma::row_major> af[4];
            wmma::fragment<wmma::matrix_b, 16, 16, 8, wmma::precision::tf32, wmma::col_major> bf[NF];
            #pragma unroll
            for (int mf = 0; mf < 4; mf++) {
                wmma::load_matrix_sync(af[mf], &sa[(wm + mf * 16) * PAD + kk], PAD);
                #pragma unroll
                for (int t = 0; t < af[mf].num_elements; t++)
                    af[mf].x[t] = wmma::__float_to_tf32(af[mf].x[t]);
            }
            #pragma unroll
            for (int nf = 0; nf < NF; nf++) {
                wmma::load_matrix_sync(bf[nf], &sb[(wn + nf * 16) * PAD + kk], PAD);
                #pragma unroll
                for (int t = 0; t < bf[nf].num_elements; t++)
                    bf[nf].x[t] = wmma::__float_to_tf32(bf[nf].x[t]);
            }
            #pragma unroll
            for (int mf = 0; mf < 4; mf++)
                #pragma unroll
                for (int nf = 0; nf < NF; nf++)
                    wmma::mma_sync(c[mf][nf], af[mf], bf[nf], c[mf][nf]);
        }
        __syncthreads();
    }

    // Epilogue: per-warp smem staging, 64x16 at pitch 20, looped over nf.
    float* stage = smem_all + warp * (64 * PAD);
    #pragma unroll
    for (int nf = 0; nf < NF; nf++) {
        #pragma unroll
        for (int mf = 0; mf < 4; mf++)
            wmma::store_matrix_sync(stage + mf * 16 * PAD, c[mf][nf], PAD, wmma::mem_row_major);
        __syncwarp();
        #pragma unroll
        for (int i = 0; i < 8; i++) {
            int idx = lane + i * 32;     // 0..255
            int r   = idx >> 2;          // 0..63
            int c4  = (idx & 3) << 2;    // 0,4,8,12
            float4 v = *reinterpret_cast<float4*>(&stage[r * PAD + c4]);
            float vv[4] = {v.x, v.y, v.z, v.w};
            #pragma unroll
            for (int t = 0; t < 4; t++) {
                float x = vv[t] + bias[jw + wn + nf * 16 + c4 + t];
                if (op == 1)      x = sigmoid_f(x);
                else if (op == 2) x = gelu_exact(x);
                vv[t] = x;
            }
            *reinterpret_cast<float4*>(
                &out[(size_t)(m0 + wm + r) * ldo + j0 + wn + nf * 16 + c4]) =
                make_float4(vv[0], vv[1], vv[2], vv[3]);
        }
        __syncwarp();
    }
}

// ---------------------------------------------------------------------------
// Pass A: per-chunk sums of the combined-gelu h (gelu already applied).
// ---------------------------------------------------------------------------
__global__ __launch_bounds__(256) void chunk_sum_kernel() {
    const int b  = blockIdx.x / NCHUNK;
    const int ch = blockIdx.x % NCHUNK;
    const int d  = threadIdx.x;  // 0..255

    float s_lo = 0.0f, s_hi = 0.0f;
    size_t base = ((size_t)(b * NN + ch * CHUNK)) * 1024 + 512;
    #pragma unroll 4
    for (int r = 0; r < CHUNK; r++) {
        float g1 = g_sh[base + (size_t)r * 1024 + d];
        float g2 = g_sh[base + (size_t)r * 1024 + 256 + d];
        s_lo += g1;
        s_hi += g1 * g2;
    }
    int pb = (b * NCHUNK + ch) * DE;
    g_part[pb + d]       = s_lo;
    g_part[pb + 256 + d] = s_hi;
}

// ---------------------------------------------------------------------------
// Block-parallel exclusive scan of chunk partials along the chunk axis.
// ---------------------------------------------------------------------------
__global__ __launch_bounds__(256) void scan_part_kernel() {
    const int b = blockIdx.x / DE;
    const int d = blockIdx.x % DE;
    const int c = threadIdx.x;          // 0..255 == NCHUNK
    const int lane = c & 31;
    const int wid  = c >> 5;

    int idx = (b * NCHUNK + c) * DE + d;
    float v = g_part[idx];

    float x = v;
    #pragma unroll
    for (int off = 1; off < 32; off <<= 1) {
        float y = __shfl_up_sync(0xFFFFFFFFu, x, off);
        if (lane >= off) x += y;
    }

    __shared__ float wsum[8];
    if (lane == 31) wsum[wid] = x;
    __syncthreads();

    __shared__ float woff[8];
    if (wid == 0 && lane < 8) {
        float t = wsum[lane];
        #pragma unroll
        for (int off = 1; off < 8; off <<= 1) {
            float y = __shfl_up_sync(0xFFu, t, off);
            if (lane >= off) t += y;
        }
        woff[lane] = t;
    }
    __syncthreads();

    float base = (wid == 0) ? 0.0f : woff[wid - 1];
    g_part[idx] = base + x - v;   // exclusive prefix
}

// ---------------------------------------------------------------------------
// Pass B: within-chunk inclusive scan with exclusive offset, then
//   o = gate * agg / (m+1 + 1e-7)
// ---------------------------------------------------------------------------
__global__ __launch_bounds__(256) void scan_apply_kernel() {
    const int b  = blockIdx.x / NCHUNK;
    const int ch = blockIdx.x % NCHUNK;
    const int d  = threadIdx.x;  // 0..255

    int pb = (b * NCHUNK + ch) * DE;
    float run_lo = g_part[pb + d];
    float run_hi = g_part[pb + 256 + d];

    #pragma unroll 4
    for (int r = 0; r < CHUNK; r++) {
        int n = ch * CHUNK + r;
        size_t row = (size_t)(b * NN + n);
        float g1 = g_sh[row * 1024 + 512 + d];
        float g2 = g_sh[row * 1024 + 768 + d];
        run_lo += g1;
        run_hi += g1 * g2;

        float rec = 1.0f / ((float)(n + 1) + 1e-7f);
        float gate1 = g_sh[row * 1024 + d];
        float gate2 = g_sh[row * 1024 + 256 + d];
        g_o[row * DE + d]       = gate1 * run_lo * rec;
        g_o[row * DE + 256 + d] = gate2 * run_hi * rec;
    }
}

// ---------------------------------------------------------------------------
// Launcher
// ---------------------------------------------------------------------------
extern "C" void kernel_launch(void* const* d_in, const int* in_sizes, int n_in,
                              void* d_out, int out_size) {
    const float* xq   = (const float*)d_in[0];
    const float* W_se = (const float*)d_in[2];
    const float* b_se = (const float*)d_in[3];
    const float* W_po = (const float*)d_in[4];
    const float* b_po = (const float*)d_in[5];
    const float* W_ag = (const float*)d_in[6];
    const float* b_ag = (const float*)d_in[7];
    float* out = (float*)d_out;

    float* sh_ptr = nullptr;
    float* o_ptr  = nullptr;
    cudaGetSymbolAddress((void**)&sh_ptr, g_sh);
    cudaGetSymbolAddress((void**)&o_ptr, g_o);

    // GEMM1+2 fused: [16384,128] x [1024,128]^T -> gate | gelu(h)
    {
        dim3 grid(TOT / BM, 1024 / 128);   // (128, 8)
        gemm_tf32_kernel<128><<<grid, 128>>>(
            xq, DIMV,
            W_se, b_se, /*op=*/1,
            W_po, b_po, /*op=*/2,
            /*splitJ=*/DE, /*K=*/DIMV,
            sh_ptr, /*ldo=*/1024);
    }

    chunk_sum_kernel<<<BB * NCHUNK, 256>>>();
    scan_part_kernel<<<BB * DE, 256>>>();
    scan_apply_kernel<<<BB * NCHUNK, 256>>>();

    // GEMM3: [16384,512] x [128,512]^T -> out
    {
        dim3 grid(TOT / BM, DIMV / 64);    // (128, 2)
        gemm_tf32_kernel<64><<<grid, 128>>>(
            o_ptr, DE,
            W_ag, b_ag, /*op=*/0,
            W_ag, b_ag, /*op=*/0,
            /*splitJ=*/1 << 30, /*K=*/DE,
            out, /*ldo=*/DIMV);
    }
}

// round 7
// speedup vs baseline: 2.0174x; 2.0174x over previous
#include <cuda_runtime.h>
#include <cuda_bf16.h>
#include <mma.h>
#include <cstdint>

using namespace nvcuda;

#define BB 4
#define NN 4096
#define DIMV 128
#define DE 512
#define TOT (BB * NN)          // 16384 rows
#define CHUNK 16
#define NCHUNK (NN / CHUNK)    // 256

// Scratch (allocation-free: __device__ globals)
// g_sh per row: [0,512) = sigmoid(s) (gate), [512,1024) = gelu(h)
__device__ float g_sh[(size_t)TOT * 1024];
__device__ float g_o[(size_t)TOT * DE];      // gated aggregation, input to final GEMM
__device__ float g_part[BB * NCHUNK * DE];   // chunk partial sums -> exclusive offsets

#define BM 128
#define BKG 16
#define PAD 20                  // smem pitch (floats); 80B = mult of 16

__device__ __forceinline__ float gelu_exact(float x) {
    return 0.5f * x * (1.0f + erff(x * 0.70710678118654752f));
}
__device__ __forceinline__ float sigmoid_f(float x) {
    return 1.0f / (1.0f + expf(-x));
}

__device__ __forceinline__ void cp_async16(void* smem_dst, const void* gmem_src) {
    unsigned int s = (unsigned int)__cvta_generic_to_shared(smem_dst);
    asm volatile("cp.async.cg.shared.global [%0], [%1], 16;\n" :: "r"(s), "l"(gmem_src));
}
__device__ __forceinline__ void cp_commit() {
    asm volatile("cp.async.commit_group;\n");
}
template <int N>
__device__ __forceinline__ void cp_wait() {
    asm volatile("cp.async.wait_group %0;\n" :: "n"(N));
}

// ---------------------------------------------------------------------------
// tf32 wmma GEMM, BM=128 x BN tile, BK=16, NST-stage cp.async pipeline.
// 256 threads = 8 warps (4 M x 2 N); warp tile 32 x (BN/2).
//   out[m, j] = op( sum_k A[m,k] * W[j,k] + bias[j] )
// W row-major [Ntot, K]. Split weight at splitJ. op: 0=none 1=sigmoid 2=gelu
// BN=128: c[2][4] (64 accum regs). BN=64: c[2][2] (round-5 proven config).
// ---------------------------------------------------------------------------
template <int BN, int NST>
__global__ __launch_bounds__(256) void gemm_tf32_kernel(
    const float* __restrict__ A, int lda,
    const float* __restrict__ W0, const float* __restrict__ bias0, int op0,
    const float* __restrict__ W1, const float* __restrict__ bias1, int op1,
    int splitJ, int K,
    float* __restrict__ out, int ldo)
{
    constexpr int NF  = BN / 32;          // b-fragments per warp
    constexpr int STG = (BM + BN) * PAD;  // floats per stage
    __shared__ float smem_all[NST * STG]; // BN=128,NST=2: 40KB; BN=64,NST=3: 45KB

    const int m0 = blockIdx.x * BM;
    const int j0 = blockIdx.y * BN;

    const float* W = W0;
    const float* bias = bias0;
    int op = op0;
    int jw = j0;
    if (j0 >= splitJ) { W = W1; bias = bias1; op = op1; jw = j0 - splitJ; }

    const int tid  = threadIdx.x;
    const int warp = tid >> 5;
    const int lane = tid & 31;
    const int wm = (warp & 3) * 32;        // warp row offset
    const int wn = (warp >> 2) * (BN / 2); // warp col offset

    const int niters = K / BKG;

    auto issue_load = [&](int it, int buf) {
        float* sa = smem_all + buf * STG;
        float* sb = sa + BM * PAD;
        int kb = it * BKG;
        // A: 128x16 = 512 float4; B: BNx16 = BN*4 float4. Total /256 per thread.
        constexpr int NLD = 2 + BN / 64;
        #pragma unroll
        for (int i = 0; i < NLD; i++) {
            int idx = tid + i * 256;
            if (idx < 512) {
                int r  = idx >> 2;
                int c4 = (idx & 3) << 2;
                cp_async16(&sa[r * PAD + c4], &A[(size_t)(m0 + r) * lda + kb + c4]);
            } else {
                int j  = idx - 512;
                int r  = j >> 2;
                int c4 = (j & 3) << 2;
                cp_async16(&sb[r * PAD + c4], &W[(size_t)(jw + r) * K + kb + c4]);
            }
        }
    };

    wmma::fragment<wmma::accumulator, 16, 16, 8, float> c[2][NF];
    #pragma unroll
    for (int i = 0; i < 2; i++)
        #pragma unroll
        for (int j = 0; j < NF; j++)
            wmma::fill_fragment(c[i][j], 0.0f);

    // Prologue: prefetch NST-1 stages
    #pragma unroll
    for (int s = 0; s < NST - 1; s++) {
        if (s < niters) issue_load(s, s);
        cp_commit();
    }

    for (int it = 0; it < niters; it++) {
        if (it + NST - 1 < niters) issue_load(it + NST - 1, (it + NST - 1) % NST);
        cp_commit();
        cp_wait<NST - 1>();    // stage `it` complete
        __syncthreads();

        float* sa = smem_all + (it % NST) * STG;
        float* sb = sa + BM * PAD;

        #pragma unroll
        for (int kk = 0; kk < BKG; kk += 8) {
            wmma::fragment<wmma::matrix_a, 16, 16, 8, wmma::precision::tf32, wmma::row_major> af[2];
            wmma::fragment<wmma::matrix_b, 16, 16, 8, wmma::precision::tf32, wmma::col_major> bf[NF];
            #pragma unroll
            for (int mf = 0; mf < 2; mf++) {
                wmma::load_matrix_sync(af[mf], &sa[(wm + mf * 16) * PAD + kk], PAD);
                #pragma unroll
                for (int t = 0; t < af[mf].num_elements; t++)
                    af[mf].x[t] = wmma::__float_to_tf32(af[mf].x[t]);
            }
            #pragma unroll
            for (int nf = 0; nf < NF; nf++) {
                wmma::load_matrix_sync(bf[nf], &sb[(wn + nf * 16) * PAD + kk], PAD);
                #pragma unroll
                for (int t = 0; t < bf[nf].num_elements; t++)
                    bf[nf].x[t] = wmma::__float_to_tf32(bf[nf].x[t]);
            }
            #pragma unroll
            for (int mf = 0; mf < 2; mf++)
                #pragma unroll
                for (int nf = 0; nf < NF; nf++)
                    wmma::mma_sync(c[mf][nf], af[mf], bf[nf], c[mf][nf]);
        }
        __syncthreads();
    }

    // Epilogue: per-warp smem staging (32x16 slabs at pitch 20), bias + op.
    float* stage = smem_all + warp * (32 * PAD);   // 8 * 640 = 5120 floats, fits
    #pragma unroll
    for (int nf = 0; nf < NF; nf++) {
        wmma::store_matrix_sync(stage,            c[0][nf], PAD, wmma::mem_row_major);
        wmma::store_matrix_sync(stage + 16 * PAD, c[1][nf], PAD, wmma::mem_row_major);
        __syncwarp();
        #pragma unroll
        for (int i = 0; i < 4; i++) {
            int idx = lane + i * 32;     // 0..127
            int r   = idx >> 2;          // 0..31
            int c4  = (idx & 3) << 2;    // 0,4,8,12
            float4 v = *reinterpret_cast<float4*>(&stage[r * PAD + c4]);
            float vv[4] = {v.x, v.y, v.z, v.w};
            #pragma unroll
            for (int t = 0; t < 4; t++) {
                float x = vv[t] + bias[jw + wn + nf * 16 + c4 + t];
                if (op == 1)      x = sigmoid_f(x);
                else if (op == 2) x = gelu_exact(x);
                vv[t] = x;
            }
            *reinterpret_cast<float4*>(
                &out[(size_t)(m0 + wm + r) * ldo + j0 + wn + nf * 16 + c4]) =
                make_float4(vv[0], vv[1], vv[2], vv[3]);
        }
        __syncwarp();
    }
}

// ---------------------------------------------------------------------------
// Pass A: per-chunk sums of the combined-gelu h (gelu already applied).
// ---------------------------------------------------------------------------
__global__ __launch_bounds__(256) void chunk_sum_kernel() {
    const int b  = blockIdx.x / NCHUNK;
    const int ch = blockIdx.x % NCHUNK;
    const int d  = threadIdx.x;  // 0..255

    float s_lo = 0.0f, s_hi = 0.0f;
    size_t base = ((size_t)(b * NN + ch * CHUNK)) * 1024 + 512;
    #pragma unroll 4
    for (int r = 0; r < CHUNK; r++) {
        float g1 = g_sh[base + (size_t)r * 1024 + d];
        float g2 = g_sh[base + (size_t)r * 1024 + 256 + d];
        s_lo += g1;
        s_hi += g1 * g2;
    }
    int pb = (b * NCHUNK + ch) * DE;
    g_part[pb + d]       = s_lo;
    g_part[pb + 256 + d] = s_hi;
}

// ---------------------------------------------------------------------------
// Block-parallel exclusive scan of chunk partials along the chunk axis.
// ---------------------------------------------------------------------------
__global__ __launch_bounds__(256) void scan_part_kernel() {
    const int b = blockIdx.x / DE;
    const int d = blockIdx.x % DE;
    const int c = threadIdx.x;          // 0..255 == NCHUNK
    const int lane = c & 31;
    const int wid  = c >> 5;

    int idx = (b * NCHUNK + c) * DE + d;
    float v = g_part[idx];

    float x = v;
    #pragma unroll
    for (int off = 1; off < 32; off <<= 1) {
        float y = __shfl_up_sync(0xFFFFFFFFu, x, off);
        if (lane >= off) x += y;
    }

    __shared__ float wsum[8];
    if (lane == 31) wsum[wid] = x;
    __syncthreads();

    __shared__ float woff[8];
    if (wid == 0 && lane < 8) {
        float t = wsum[lane];
        #pragma unroll
        for (int off = 1; off < 8; off <<= 1) {
            float y = __shfl_up_sync(0xFFu, t, off);
            if (lane >= off) t += y;
        }
        woff[lane] = t;
    }
    __syncthreads();

    float base = (wid == 0) ? 0.0f : woff[wid - 1];
    g_part[idx] = base + x - v;   // exclusive prefix
}

// ---------------------------------------------------------------------------
// Pass B: within-chunk inclusive scan with exclusive offset, then
//   o = gate * agg / (m+1 + 1e-7)
// ---------------------------------------------------------------------------
__global__ __launch_bounds__(256) void scan_apply_kernel() {
    const int b  = blockIdx.x / NCHUNK;
    const int ch = blockIdx.x % NCHUNK;
    const int d  = threadIdx.x;  // 0..255

    int pb = (b * NCHUNK + ch) * DE;
    float run_lo = g_part[pb + d];
    float run_hi = g_part[pb + 256 + d];

    #pragma unroll 4
    for (int r = 0; r < CHUNK; r++) {
        int n = ch * CHUNK + r;
        size_t row = (size_t)(b * NN + n);
        float g1 = g_sh[row * 1024 + 512 + d];
        float g2 = g_sh[row * 1024 + 768 + d];
        run_lo += g1;
        run_hi += g1 * g2;

        float rec = 1.0f / ((float)(n + 1) + 1e-7f);
        float gate1 = g_sh[row * 1024 + d];
        float gate2 = g_sh[row * 1024 + 256 + d];
        g_o[row * DE + d]       = gate1 * run_lo * rec;
        g_o[row * DE + 256 + d] = gate2 * run_hi * rec;
    }
}

// ---------------------------------------------------------------------------
// Launcher
// ---------------------------------------------------------------------------
extern "C" void kernel_launch(void* const* d_in, const int* in_sizes, int n_in,
                              void* d_out, int out_size) {
    const float* xq   = (const float*)d_in[0];
    const float* W_se = (const float*)d_in[2];
    const float* b_se = (const float*)d_in[3];
    const float* W_po = (const float*)d_in[4];
    const float* b_po = (const float*)d_in[5];
    const float* W_ag = (const float*)d_in[6];
    const float* b_ag = (const float*)d_in[7];
    float* out = (float*)d_out;

    float* sh_ptr = nullptr;
    float* o_ptr  = nullptr;
    cudaGetSymbolAddress((void**)&sh_ptr, g_sh);
    cudaGetSymbolAddress((void**)&o_ptr, g_o);

    // GEMM1+2 fused: [16384,128] x [1024,128]^T -> gate | gelu(h)
    {
        dim3 grid(TOT / BM, 1024 / 128);   // (128, 8)
        gemm_tf32_kernel<128, 2><<<grid, 256>>>(
            xq, DIMV,
            W_se, b_se, /*op=*/1,
            W_po, b_po, /*op=*/2,
            /*splitJ=*/DE, /*K=*/DIMV,
            sh_ptr, /*ldo=*/1024);
    }

    chunk_sum_kernel<<<BB * NCHUNK, 256>>>();
    scan_part_kernel<<<BB * DE, 256>>>();
    scan_apply_kernel<<<BB * NCHUNK, 256>>>();

    // GEMM3: [16384,512] x [128,512]^T -> out  (round-5 proven config)
    {
        dim3 grid(TOT / BM, DIMV / 64);    // (128, 2)
        gemm_tf32_kernel<64, 3><<<grid, 256>>>(
            o_ptr, DE,
            W_ag, b_ag, /*op=*/0,
            W_ag, b_ag, /*op=*/0,
            /*splitJ=*/1 << 30, /*K=*/DE,
            out, /*ldo=*/DIMV);
    }
}

// round 9
// speedup vs baseline: 3.4482x; 1.7092x over previous
#include <cuda_runtime.h>
#include <cuda_fp16.h>
#include <mma.h>
#include <cstdint>

using namespace nvcuda;

#define BB 4
#define NN 4096
#define DIMV 128
#define DE 512
#define TOT (BB * NN)          // 16384 rows
#define CHUNK 16
#define NCHUNK (NN / CHUNK)    // 256

// Scratch (allocation-free: __device__ globals)
// g_sh per row: [0,512) = sigmoid(s) (gate), [512,1024) = gelu(h)
__device__ float  g_sh[(size_t)TOT * 1024];
__device__ __half g_o_h[(size_t)TOT * DE];    // gated aggregation (fp16), input to GEMM3
__device__ float  g_part[BB * NCHUNK * DE];   // chunk partial sums -> exclusive offsets
__device__ __half g_xq_h[(size_t)TOT * DIMV]; // fp16 copy of xq
__device__ __half g_w1_h[1024 * DIMV];        // [W_se; W_po] fp16, rows 0..1023
__device__ __half g_w3_h[DIMV * DE];          // W_ag fp16
__device__ float  g_b1[1024];                 // [b_se; b_po]

#define BM 128
#define BKG 32
#define PADH 40                 // half pitch: 80 B, multiple of 16

__device__ __forceinline__ float gelu_exact(float x) {
    return 0.5f * x * (1.0f + erff(x * 0.70710678118654752f));
}
__device__ __forceinline__ float sigmoid_f(float x) {
    return 1.0f / (1.0f + expf(-x));
}

__device__ __forceinline__ void cp_async16(void* smem_dst, const void* gmem_src) {
    unsigned s = (unsigned)__cvta_generic_to_shared(smem_dst);
    asm volatile("cp.async.cg.shared.global [%0], [%1], 16;" :: "r"(s), "l"(gmem_src));
}
__device__ __forceinline__ void cp_commit() {
    asm volatile("cp.async.commit_group;");
}
template <int N>
__device__ __forceinline__ void cp_wait() {
    asm volatile("cp.async.wait_group %0;" :: "n"(N));
}

// ---------------------------------------------------------------------------
// Conversion kernels
// ---------------------------------------------------------------------------
__global__ __launch_bounds__(256) void conv_xq_kernel(const float* __restrict__ x) {
    int i = (blockIdx.x * 256 + threadIdx.x) * 4;   // TOT*DIMV = 2,097,152 elems
    float4 v = *reinterpret_cast<const float4*>(&x[i]);
    __half2 h0 = __floats2half2_rn(v.x, v.y);
    __half2 h1 = __floats2half2_rn(v.z, v.w);
    *reinterpret_cast<__half2*>(&g_xq_h[i])     = h0;
    *reinterpret_cast<__half2*>(&g_xq_h[i + 2]) = h1;
}

__global__ __launch_bounds__(256) void conv_w_kernel(
    const float* __restrict__ wse, const float* __restrict__ wpo,
    const float* __restrict__ wag,
    const float* __restrict__ bse, const float* __restrict__ bpo)
{
    int i = blockIdx.x * 256 + threadIdx.x;    // grid covers 65536
    g_w1_h[i]         = __float2half(wse[i]);
    g_w1_h[65536 + i] = __float2half(wpo[i]);
    g_w3_h[i]         = __float2half(wag[i]);
    if (i < 512) { g_b1[i] = bse[i]; g_b1[512 + i] = bpo[i]; }
}

// ---------------------------------------------------------------------------
// fp16 wmma GEMM (fp32 accum), BM=128 x BN tile, BK=32, NST-stage cp.async.
// 256 threads = 8 warps (4 M x 2 N); warp tile 32 x (BN/2).
//   out[m, j] = op( sum_k A[m,k] * W[j,k] + bias[j] ),  op chosen by j0<opSplit
// ---------------------------------------------------------------------------
template <int BN, int NST>
__global__ __launch_bounds__(256) void gemm_f16_kernel(
    const __half* __restrict__ A, int lda,
    const __half* __restrict__ W, const float* __restrict__ bias,
    int op0, int op1, int opSplit, int K,
    float* __restrict__ out, int ldo)
{
    constexpr int NF  = BN / 32;            // b-fragments per warp
    constexpr int STG = (BM + BN) * PADH;   // halves per stage
    __shared__ __half smem_all[NST * STG];  // BN=128,NST=2: 40KB; BN=64,NST=3: 45KB

    const int m0 = blockIdx.x * BM;
    const int j0 = blockIdx.y * BN;
    const int op = (j0 < opSplit) ? op0 : op1;

    const int tid  = threadIdx.x;
    const int warp = tid >> 5;
    const int lane = tid & 31;
    const int wm = (warp & 3) * 32;         // warp row offset
    const int wn = (warp >> 2) * (BN / 2);  // warp col offset

    const int niters = K / BKG;

    auto issue_load = [&](int it, int buf) {
        __half* sa = smem_all + buf * STG;
        __half* sb = sa + BM * PADH;
        int kb = it * BKG;
        // A: 128x32 halves = 512 cp16; B: BNx32 = BN*4 cp16. / 256 thr.
        constexpr int NLD = 2 + BN / 64;
        #pragma unroll
        for (int i = 0; i < NLD; i++) {
            int idx = tid + i * 256;
            if (idx < 512) {
                int r  = idx >> 2;
                int c8 = (idx & 3) << 3;
                cp_async16(&sa[r * PADH + c8], &A[(size_t)(m0 + r) * lda + kb + c8]);
            } else {
                int j  = idx - 512;
                int r  = j >> 2;
                int c8 = (j & 3) << 3;
                cp_async16(&sb[r * PADH + c8], &W[(size_t)(j0 + r) * K + kb + c8]);
            }
        }
    };

    wmma::fragment<wmma::accumulator, 16, 16, 16, float> c[2][NF];
    #pragma unroll
    for (int i = 0; i < 2; i++)
        #pragma unroll
        for (int j = 0; j < NF; j++)
            wmma::fill_fragment(c[i][j], 0.0f);

    #pragma unroll
    for (int s = 0; s < NST - 1; s++) {
        if (s < niters) issue_load(s, s);
        cp_commit();
    }

    for (int it = 0; it < niters; it++) {
        if (it + NST - 1 < niters) issue_load(it + NST - 1, (it + NST - 1) % NST);
        cp_commit();
        cp_wait<NST - 1>();    // stage `it` complete
        __syncthreads();

        __half* sa = smem_all + (it % NST) * STG;
        __half* sb = sa + BM * PADH;

        #pragma unroll
        for (int kk = 0; kk < BKG; kk += 16) {
            wmma::fragment<wmma::matrix_a, 16, 16, 16, __half, wmma::row_major> af[2];
            wmma::fragment<wmma::matrix_b, 16, 16, 16, __half, wmma::col_major> bf[NF];
            #pragma unroll
            for (int mf = 0; mf < 2; mf++)
                wmma::load_matrix_sync(af[mf], &sa[(wm + mf * 16) * PADH + kk], PADH);
            #pragma unroll
            for (int nf = 0; nf < NF; nf++)
                wmma::load_matrix_sync(bf[nf], &sb[(wn + nf * 16) * PADH + kk], PADH);
            #pragma unroll
            for (int mf = 0; mf < 2; mf++)
                #pragma unroll
                for (int nf = 0; nf < NF; nf++)
                    wmma::mma_sync(c[mf][nf], af[mf], bf[nf], c[mf][nf]);
        }
        __syncthreads();
    }

    // Epilogue: per-warp fp32 smem staging (32x16 at pitch 20), bias + op.
    float* stage = reinterpret_cast<float*>(smem_all) + warp * (32 * 20);
    #pragma unroll
    for (int nf = 0; nf < NF; nf++) {
        wmma::store_matrix_sync(stage,           c[0][nf], 20, wmma::mem_row_major);
        wmma::store_matrix_sync(stage + 16 * 20, c[1][nf], 20, wmma::mem_row_major);
        __syncwarp();
        #pragma unroll
        for (int i = 0; i < 4; i++) {
            int idx = lane + i * 32;     // 0..127
            int r   = idx >> 2;          // 0..31
            int c4  = (idx & 3) << 2;    // 0,4,8,12
            float4 v = *reinterpret_cast<float4*>(&stage[r * 20 + c4]);
            float vv[4] = {v.x, v.y, v.z, v.w};
            #pragma unroll
            for (int t = 0; t < 4; t++) {
                float x = vv[t] + bias[j0 + wn + nf * 16 + c4 + t];
                if (op == 1)      x = sigmoid_f(x);
                else if (op == 2) x = gelu_exact(x);
                vv[t] = x;
            }
            *reinterpret_cast<float4*>(
                &out[(size_t)(m0 + wm + r) * ldo + j0 + wn + nf * 16 + c4]) =
                make_float4(vv[0], vv[1], vv[2], vv[3]);
        }
        __syncwarp();
    }
}

// ---------------------------------------------------------------------------
// Pass A: per-chunk sums of the combined-gelu h (gelu already applied).
// ---------------------------------------------------------------------------
__global__ __launch_bounds__(256) void chunk_sum_kernel() {
    const int b  = blockIdx.x / NCHUNK;
    const int ch = blockIdx.x % NCHUNK;
    const int d  = threadIdx.x;  // 0..255

    float s_lo = 0.0f, s_hi = 0.0f;
    size_t base = ((size_t)(b * NN + ch * CHUNK)) * 1024 + 512;
    #pragma unroll 4
    for (int r = 0; r < CHUNK; r++) {
        float g1 = g_sh[base + (size_t)r * 1024 + d];
        float g2 = g_sh[base + (size_t)r * 1024 + 256 + d];
        s_lo += g1;
        s_hi += g1 * g2;
    }
    int pb = (b * NCHUNK + ch) * DE;
    g_part[pb + d]       = s_lo;
    g_part[pb + 256 + d] = s_hi;
}

// ---------------------------------------------------------------------------
// Block-parallel exclusive scan of chunk partials along the chunk axis.
// ---------------------------------------------------------------------------
__global__ __launch_bounds__(256) void scan_part_kernel() {
    const int b = blockIdx.x / DE;
    const int d = blockIdx.x % DE;
    const int c = threadIdx.x;          // 0..255 == NCHUNK
    const int lane = c & 31;
    const int wid  = c >> 5;

    int idx = (b * NCHUNK + c) * DE + d;
    float v = g_part[idx];

    float x = v;
    #pragma unroll
    for (int off = 1; off < 32; off <<= 1) {
        float y = __shfl_up_sync(0xFFFFFFFFu, x, off);
        if (lane >= off) x += y;
    }

    __shared__ float wsum[8];
    if (lane == 31) wsum[wid] = x;
    __syncthreads();

    __shared__ float woff[8];
    if (wid == 0 && lane < 8) {
        float t = wsum[lane];
        #pragma unroll
        for (int off = 1; off < 8; off <<= 1) {
            float y = __shfl_up_sync(0xFFu, t, off);
            if (lane >= off) t += y;
        }
        woff[lane] = t;
    }
    __syncthreads();

    float base = (wid == 0) ? 0.0f : woff[wid - 1];
    g_part[idx] = base + x - v;   // exclusive prefix
}

// ---------------------------------------------------------------------------
// Pass B: within-chunk inclusive scan with exclusive offset, then
//   o = gate * agg / (m+1 + 1e-7)   -> stored fp16 for GEMM3
// ---------------------------------------------------------------------------
__global__ __launch_bounds__(256) void scan_apply_kernel() {
    const int b  = blockIdx.x / NCHUNK;
    const int ch = blockIdx.x % NCHUNK;
    const int d  = threadIdx.x;  // 0..255

    int pb = (b * NCHUNK + ch) * DE;
    float run_lo = g_part[pb + d];
    float run_hi = g_part[pb + 256 + d];

    #pragma unroll 4
    for (int r = 0; r < CHUNK; r++) {
        int n = ch * CHUNK + r;
        size_t row = (size_t)(b * NN + n);
        float g1 = g_sh[row * 1024 + 512 + d];
        float g2 = g_sh[row * 1024 + 768 + d];
        run_lo += g1;
        run_hi += g1 * g2;

        float rec = 1.0f / ((float)(n + 1) + 1e-7f);
        float gate1 = g_sh[row * 1024 + d];
        float gate2 = g_sh[row * 1024 + 256 + d];
        g_o_h[row * DE + d]       = __float2half(gate1 * run_lo * rec);
        g_o_h[row * DE + 256 + d] = __float2half(gate2 * run_hi * rec);
    }
}

// ---------------------------------------------------------------------------
// Launcher
// ---------------------------------------------------------------------------
extern "C" void kernel_launch(void* const* d_in, const int* in_sizes, int n_in,
                              void* d_out, int out_size) {
    const float* xq   = (const float*)d_in[0];
    const float* W_se = (const float*)d_in[2];
    const float* b_se = (const float*)d_in[3];
    const float* W_po = (const float*)d_in[4];
    const float* b_po = (const float*)d_in[5];
    const float* W_ag = (const float*)d_in[6];
    const float* b_ag = (const float*)d_in[7];
    float* out = (float*)d_out;

    float*  sh_ptr  = nullptr;
    __half* oh_ptr  = nullptr;
    __half* xqh_ptr = nullptr;
    __half* w1_ptr  = nullptr;
    __half* w3_ptr  = nullptr;
    float*  b1_ptr  = nullptr;
    cudaGetSymbolAddress((void**)&sh_ptr,  g_sh);
    cudaGetSymbolAddress((void**)&oh_ptr,  g_o_h);
    cudaGetSymbolAddress((void**)&xqh_ptr, g_xq_h);
    cudaGetSymbolAddress((void**)&w1_ptr,  g_w1_h);
    cudaGetSymbolAddress((void**)&w3_ptr,  g_w3_h);
    cudaGetSymbolAddress((void**)&b1_ptr,  g_b1);

    // fp16 conversions
    conv_xq_kernel<<<(TOT * DIMV) / 1024, 256>>>(xq);
    conv_w_kernel<<<65536 / 256, 256>>>(W_se, W_po, W_ag, b_se, b_po);

    // GEMM1+2 fused: [16384,128] x [1024,128]^T -> gate | gelu(h)
    {
        dim3 grid(TOT / BM, 1024 / 128);   // (128, 8)
        gemm_f16_kernel<128, 2><<<grid, 256>>>(
            xqh_ptr, DIMV,
            w1_ptr, b1_ptr,
            /*op0=*/1, /*op1=*/2, /*opSplit=*/DE, /*K=*/DIMV,
            sh_ptr, /*ldo=*/1024);
    }

    chunk_sum_kernel<<<BB * NCHUNK, 256>>>();
    scan_part_kernel<<<BB * DE, 256>>>();
    scan_apply_kernel<<<BB * NCHUNK, 256>>>();

    // GEMM3: [16384,512] x [128,512]^T -> out
    {
        dim3 grid(TOT / BM, DIMV / 64);    // (128, 2)
        gemm_f16_kernel<64, 3><<<grid, 256>>>(
            oh_ptr, DE,
            w3_ptr, b_ag,
            /*op0=*/0, /*op1=*/0, /*opSplit=*/1 << 30, /*K=*/DE,
            out, /*ldo=*/DIMV);
    }
}

// round 10
// speedup vs baseline: 3.7799x; 1.0962x over previous
#include <cuda_runtime.h>
#include <cuda_fp16.h>
#include <mma.h>
#include <cstdint>

using namespace nvcuda;

#define BB 4
#define NN 4096
#define DIMV 128
#define DE 512
#define TOT (BB * NN)          // 16384 rows
#define CHUNK 16
#define NCHUNK (NN / CHUNK)    // 256

// Scratch (allocation-free: __device__ globals)
// g_sh_h per row (fp16): [0,512) = sigmoid(s) gate, [512,1024) = gelu(h)
__device__ __half g_sh_h[(size_t)TOT * 1024];
__device__ __half g_o_h[(size_t)TOT * DE];    // gated aggregation (fp16), input to GEMM3
__device__ float  g_part[BB * NCHUNK * DE];   // chunk partial sums -> exclusive offsets
__device__ __half g_xq_h[(size_t)TOT * DIMV]; // fp16 copy of xq
__device__ __half g_w1_h[1024 * DIMV];        // [W_se; W_po] fp16
__device__ __half g_w3_h[DIMV * DE];          // W_ag fp16
__device__ float  g_b1[1024];                 // [b_se; b_po]

#define BM 128
#define BKG 32
#define PADH 40                 // half pitch: 80 B, multiple of 16

__device__ __forceinline__ float gelu_exact(float x) {
    return 0.5f * x * (1.0f + erff(x * 0.70710678118654752f));
}
__device__ __forceinline__ float sigmoid_f(float x) {
    return 1.0f / (1.0f + expf(-x));
}

__device__ __forceinline__ void cp_async16(void* smem_dst, const void* gmem_src) {
    unsigned s = (unsigned)__cvta_generic_to_shared(smem_dst);
    asm volatile("cp.async.cg.shared.global [%0], [%1], 16;" :: "r"(s), "l"(gmem_src));
}
__device__ __forceinline__ void cp_commit() {
    asm volatile("cp.async.commit_group;");
}
template <int N>
__device__ __forceinline__ void cp_wait() {
    asm volatile("cp.async.wait_group %0;" :: "n"(N));
}

// ---------------------------------------------------------------------------
// Conversion kernels
// ---------------------------------------------------------------------------
__global__ __launch_bounds__(256) void conv_xq_kernel(const float* __restrict__ x) {
    int i = (blockIdx.x * 256 + threadIdx.x) * 4;
    float4 v = *reinterpret_cast<const float4*>(&x[i]);
    *reinterpret_cast<__half2*>(&g_xq_h[i])     = __floats2half2_rn(v.x, v.y);
    *reinterpret_cast<__half2*>(&g_xq_h[i + 2]) = __floats2half2_rn(v.z, v.w);
}

__global__ __launch_bounds__(256) void conv_w_kernel(
    const float* __restrict__ wse, const float* __restrict__ wpo,
    const float* __restrict__ wag,
    const float* __restrict__ bse, const float* __restrict__ bpo)
{
    int i = blockIdx.x * 256 + threadIdx.x;    // grid covers 65536
    g_w1_h[i]         = __float2half(wse[i]);
    g_w1_h[65536 + i] = __float2half(wpo[i]);
    g_w3_h[i]         = __float2half(wag[i]);
    if (i < 512) { g_b1[i] = bse[i]; g_b1[512 + i] = bpo[i]; }
}

// ---------------------------------------------------------------------------
// fp16 wmma GEMM (fp32 accum), BM=128 x BN tile, BK=32, NST-stage cp.async.
// 256 threads = 8 warps (4 M x 2 N); warp tile 32 x (BN/2).
//   out[m, j] = op( sum_k A[m,k] * W[j,k] + bias[j] ),  op chosen by j0<opSplit
// OutT: float (GEMM3) or __half (GEMM1 -> g_sh_h)
// ---------------------------------------------------------------------------
template <int BN, int NST, typename OutT>
__global__ __launch_bounds__(256) void gemm_f16_kernel(
    const __half* __restrict__ A, int lda,
    const __half* __restrict__ W, const float* __restrict__ bias,
    int op0, int op1, int opSplit, int K,
    OutT* __restrict__ out, int ldo)
{
    constexpr int NF  = BN / 32;
    constexpr int STG = (BM + BN) * PADH;
    __shared__ __half smem_all[NST * STG];

    const int m0 = blockIdx.x * BM;
    const int j0 = blockIdx.y * BN;
    const int op = (j0 < opSplit) ? op0 : op1;

    const int tid  = threadIdx.x;
    const int warp = tid >> 5;
    const int lane = tid & 31;
    const int wm = (warp & 3) * 32;
    const int wn = (warp >> 2) * (BN / 2);

    const int niters = K / BKG;

    auto issue_load = [&](int it, int buf) {
        __half* sa = smem_all + buf * STG;
        __half* sb = sa + BM * PADH;
        int kb = it * BKG;
        constexpr int NLD = 2 + BN / 64;
        #pragma unroll
        for (int i = 0; i < NLD; i++) {
            int idx = tid + i * 256;
            if (idx < 512) {
                int r  = idx >> 2;
                int c8 = (idx & 3) << 3;
                cp_async16(&sa[r * PADH + c8], &A[(size_t)(m0 + r) * lda + kb + c8]);
            } else {
                int j  = idx - 512;
                int r  = j >> 2;
                int c8 = (j & 3) << 3;
                cp_async16(&sb[r * PADH + c8], &W[(size_t)(j0 + r) * K + kb + c8]);
            }
        }
    };

    wmma::fragment<wmma::accumulator, 16, 16, 16, float> c[2][NF];
    #pragma unroll
    for (int i = 0; i < 2; i++)
        #pragma unroll
        for (int j = 0; j < NF; j++)
            wmma::fill_fragment(c[i][j], 0.0f);

    #pragma unroll
    for (int s = 0; s < NST - 1; s++) {
        if (s < niters) issue_load(s, s);
        cp_commit();
    }

    for (int it = 0; it < niters; it++) {
        if (it + NST - 1 < niters) issue_load(it + NST - 1, (it + NST - 1) % NST);
        cp_commit();
        cp_wait<NST - 1>();
        __syncthreads();

        __half* sa = smem_all + (it % NST) * STG;
        __half* sb = sa + BM * PADH;

        #pragma unroll
        for (int kk = 0; kk < BKG; kk += 16) {
            wmma::fragment<wmma::matrix_a, 16, 16, 16, __half, wmma::row_major> af[2];
            wmma::fragment<wmma::matrix_b, 16, 16, 16, __half, wmma::col_major> bf[NF];
            #pragma unroll
            for (int mf = 0; mf < 2; mf++)
                wmma::load_matrix_sync(af[mf], &sa[(wm + mf * 16) * PADH + kk], PADH);
            #pragma unroll
            for (int nf = 0; nf < NF; nf++)
                wmma::load_matrix_sync(bf[nf], &sb[(wn + nf * 16) * PADH + kk], PADH);
            #pragma unroll
            for (int mf = 0; mf < 2; mf++)
                #pragma unroll
                for (int nf = 0; nf < NF; nf++)
                    wmma::mma_sync(c[mf][nf], af[mf], bf[nf], c[mf][nf]);
        }
        __syncthreads();
    }

    // Epilogue: per-warp fp32 smem staging (32x16 at pitch 20), bias + op.
    float* stage = reinterpret_cast<float*>(smem_all) + warp * (32 * 20);
    #pragma unroll
    for (int nf = 0; nf < NF; nf++) {
        wmma::store_matrix_sync(stage,           c[0][nf], 20, wmma::mem_row_major);
        wmma::store_matrix_sync(stage + 16 * 20, c[1][nf], 20, wmma::mem_row_major);
        __syncwarp();
        #pragma unroll
        for (int i = 0; i < 4; i++) {
            int idx = lane + i * 32;     // 0..127
            int r   = idx >> 2;          // 0..31
            int c4  = (idx & 3) << 2;    // 0,4,8,12
            float4 v = *reinterpret_cast<float4*>(&stage[r * 20 + c4]);
            float vv[4] = {v.x, v.y, v.z, v.w};
            #pragma unroll
            for (int t = 0; t < 4; t++) {
                float x = vv[t] + bias[j0 + wn + nf * 16 + c4 + t];
                if (op == 1)      x = sigmoid_f(x);
                else if (op == 2) x = gelu_exact(x);
                vv[t] = x;
            }
            OutT* dst = &out[(size_t)(m0 + wm + r) * ldo + j0 + wn + nf * 16 + c4];
            if (sizeof(OutT) == 2) {
                __half2 h0 = __floats2half2_rn(vv[0], vv[1]);
                __half2 h1 = __floats2half2_rn(vv[2], vv[3]);
                uint2 u;
                u.x = *reinterpret_cast<unsigned*>(&h0);
                u.y = *reinterpret_cast<unsigned*>(&h1);
                *reinterpret_cast<uint2*>(dst) = u;
            } else {
                *reinterpret_cast<float4*>(dst) = make_float4(vv[0], vv[1], vv[2], vv[3]);
            }
        }
        __syncwarp();
    }
}

// ---------------------------------------------------------------------------
// Pass A: per-chunk sums of the combined-gelu h (fp16 source).
// Thread d: lo = g[d], hi = g[d] * g[d+256]
// ---------------------------------------------------------------------------
__global__ __launch_bounds__(256) void chunk_sum_kernel() {
    const int b  = blockIdx.x / NCHUNK;
    const int ch = blockIdx.x % NCHUNK;
    const int d  = threadIdx.x;  // 0..255

    float s_lo = 0.0f, s_hi = 0.0f;
    size_t base = ((size_t)(b * NN + ch * CHUNK)) * 1024 + 512;
    #pragma unroll 4
    for (int r = 0; r < CHUNK; r++) {
        float g1 = __half2float(g_sh_h[base + (size_t)r * 1024 + d]);
        float g2 = __half2float(g_sh_h[base + (size_t)r * 1024 + 256 + d]);
        s_lo += g1;
        s_hi += g1 * g2;
    }
    int pb = (b * NCHUNK + ch) * DE;
    g_part[pb + d]       = s_lo;
    g_part[pb + 256 + d] = s_hi;
}

// ---------------------------------------------------------------------------
// Block-parallel exclusive scan of chunk partials along the chunk axis.
// ---------------------------------------------------------------------------
__global__ __launch_bounds__(256) void scan_part_kernel() {
    const int b = blockIdx.x / DE;
    const int d = blockIdx.x % DE;
    const int c = threadIdx.x;          // 0..255 == NCHUNK
    const int lane = c & 31;
    const int wid  = c >> 5;

    int idx = (b * NCHUNK + c) * DE + d;
    float v = g_part[idx];

    float x = v;
    #pragma unroll
    for (int off = 1; off < 32; off <<= 1) {
        float y = __shfl_up_sync(0xFFFFFFFFu, x, off);
        if (lane >= off) x += y;
    }

    __shared__ float wsum[8];
    if (lane == 31) wsum[wid] = x;
    __syncthreads();

    __shared__ float woff[8];
    if (wid == 0 && lane < 8) {
        float t = wsum[lane];
        #pragma unroll
        for (int off = 1; off < 8; off <<= 1) {
            float y = __shfl_up_sync(0xFFu, t, off);
            if (lane >= off) t += y;
        }
        woff[lane] = t;
    }
    __syncthreads();

    float base = (wid == 0) ? 0.0f : woff[wid - 1];
    g_part[idx] = base + x - v;   // exclusive prefix
}

// ---------------------------------------------------------------------------
// Pass B: within-chunk inclusive scan with exclusive offset, then
//   o = gate * agg / (m+1 + 1e-7)   -> stored fp16 for GEMM3
// ---------------------------------------------------------------------------
__global__ __launch_bounds__(256) void scan_apply_kernel() {
    const int b  = blockIdx.x / NCHUNK;
    const int ch = blockIdx.x % NCHUNK;
    const int d  = threadIdx.x;  // 0..255

    int pb = (b * NCHUNK + ch) * DE;
    float run_lo = g_part[pb + d];
    float run_hi = g_part[pb + 256 + d];

    #pragma unroll 4
    for (int r = 0; r < CHUNK; r++) {
        int n = ch * CHUNK + r;
        size_t row = (size_t)(b * NN + n);
        float g1 = __half2float(g_sh_h[row * 1024 + 512 + d]);
        float g2 = __half2float(g_sh_h[row * 1024 + 768 + d]);
        run_lo += g1;
        run_hi += g1 * g2;

        float rec = 1.0f / ((float)(n + 1) + 1e-7f);
        float gate1 = __half2float(g_sh_h[row * 1024 + d]);
        float gate2 = __half2float(g_sh_h[row * 1024 + 256 + d]);
        g_o_h[row * DE + d]       = __float2half(gate1 * run_lo * rec);
        g_o_h[row * DE + 256 + d] = __float2half(gate2 * run_hi * rec);
    }
}

// ---------------------------------------------------------------------------
// Launcher
// ---------------------------------------------------------------------------
extern "C" void kernel_launch(void* const* d_in, const int* in_sizes, int n_in,
                              void* d_out, int out_size) {
    const float* xq   = (const float*)d_in[0];
    const float* W_se = (const float*)d_in[2];
    const float* b_se = (const float*)d_in[3];
    const float* W_po = (const float*)d_in[4];
    const float* b_po = (const float*)d_in[5];
    const float* W_ag = (const float*)d_in[6];
    const float* b_ag = (const float*)d_in[7];
    float* out = (float*)d_out;

    __half* shh_ptr = nullptr;
    __half* oh_ptr  = nullptr;
    __half* xqh_ptr = nullptr;
    __half* w1_ptr  = nullptr;
    __half* w3_ptr  = nullptr;
    float*  b1_ptr  = nullptr;
    cudaGetSymbolAddress((void**)&shh_ptr, g_sh_h);
    cudaGetSymbolAddress((void**)&oh_ptr,  g_o_h);
    cudaGetSymbolAddress((void**)&xqh_ptr, g_xq_h);
    cudaGetSymbolAddress((void**)&w1_ptr,  g_w1_h);
    cudaGetSymbolAddress((void**)&w3_ptr,  g_w3_h);
    cudaGetSymbolAddress((void**)&b1_ptr,  g_b1);

    // fp16 conversions
    conv_xq_kernel<<<(TOT * DIMV) / 1024, 256>>>(xq);
    conv_w_kernel<<<65536 / 256, 256>>>(W_se, W_po, W_ag, b_se, b_po);

    // GEMM1+2 fused: [16384,128] x [1024,128]^T -> gate | gelu(h), fp16 out
    {
        dim3 grid(TOT / BM, 1024 / 128);   // (128, 8)
        gemm_f16_kernel<128, 2, __half><<<grid, 256>>>(
            xqh_ptr, DIMV,
            w1_ptr, b1_ptr,
            /*op0=*/1, /*op1=*/2, /*opSplit=*/DE, /*K=*/DIMV,
            shh_ptr, /*ldo=*/1024);
    }

    chunk_sum_kernel<<<BB * NCHUNK, 256>>>();
    scan_part_kernel<<<BB * DE, 256>>>();
    scan_apply_kernel<<<BB * NCHUNK, 256>>>();

    // GEMM3: [16384,512] x [128,512]^T -> out (fp32)
    {
        dim3 grid(TOT / BM, DIMV / 64);    // (128, 2)
        gemm_f16_kernel<64, 3, float><<<grid, 256>>>(
            oh_ptr, DE,
            w3_ptr, b_ag,
            /*op0=*/0, /*op1=*/0, /*opSplit=*/1 << 30, /*K=*/DE,
            out, /*ldo=*/DIMV);
    }
}

// round 11
// speedup vs baseline: 3.8482x; 1.0181x over previous
#include <cuda_runtime.h>
#include <cuda_fp16.h>
#include <mma.h>
#include <cstdint>

using namespace nvcuda;

#define BB 4
#define NN 4096
#define DIMV 128
#define DE 512
#define TOT (BB * NN)          // 16384 rows
#define CHUNK 16
#define NCHUNK (NN / CHUNK)    // 256

// Scratch (allocation-free: __device__ globals)
// g_sh_h per row (fp16): [0,512) = sigmoid(s) gate, [512,1024) = gelu(h)
__device__ __half g_sh_h[(size_t)TOT * 1024];
__device__ __half g_o_h[(size_t)TOT * DE];    // gated aggregation (fp16), input to GEMM3
__device__ float  g_part[BB * NCHUNK * DE];   // chunk partial sums -> exclusive offsets
__device__ __half g_xq_h[(size_t)TOT * DIMV]; // fp16 copy of xq
__device__ __half g_w1_h[1024 * DIMV];        // [W_se; W_po] fp16
__device__ __half g_w3_h[DIMV * DE];          // W_ag fp16
__device__ float  g_b1[1024];                 // [b_se; b_po]

#define BM 128
#define BKG 32
#define PADH 40                 // half pitch: 80 B, multiple of 16

__device__ __forceinline__ float gelu_exact(float x) {
    return 0.5f * x * (1.0f + erff(x * 0.70710678118654752f));
}
__device__ __forceinline__ float sigmoid_f(float x) {
    return 1.0f / (1.0f + expf(-x));
}

__device__ __forceinline__ void cp_async16(void* smem_dst, const void* gmem_src) {
    unsigned s = (unsigned)__cvta_generic_to_shared(smem_dst);
    asm volatile("cp.async.cg.shared.global [%0], [%1], 16;" :: "r"(s), "l"(gmem_src));
}
__device__ __forceinline__ void cp_commit() {
    asm volatile("cp.async.commit_group;");
}
template <int N>
__device__ __forceinline__ void cp_wait() {
    asm volatile("cp.async.wait_group %0;" :: "n"(N));
}

// ---------------------------------------------------------------------------
// Merged conversion kernel (one launch)
// ---------------------------------------------------------------------------
__global__ __launch_bounds__(256) void conv_all_kernel(
    const float* __restrict__ x,
    const float* __restrict__ wse, const float* __restrict__ wpo,
    const float* __restrict__ wag,
    const float* __restrict__ bse, const float* __restrict__ bpo)
{
    int i = blockIdx.x * 256 + threadIdx.x;    // grid: 2048*256 = 524288
    {   // xq: 2,097,152 elems = 524,288 float4 slots
        int e = i * 4;
        float4 v = *reinterpret_cast<const float4*>(&x[e]);
        *reinterpret_cast<__half2*>(&g_xq_h[e])     = __floats2half2_rn(v.x, v.y);
        *reinterpret_cast<__half2*>(&g_xq_h[e + 2]) = __floats2half2_rn(v.z, v.w);
    }
    if (i < 65536) {
        g_w1_h[i]         = __float2half(wse[i]);
        g_w1_h[65536 + i] = __float2half(wpo[i]);
        g_w3_h[i]         = __float2half(wag[i]);
        if (i < 512) { g_b1[i] = bse[i]; g_b1[512 + i] = bpo[i]; }
    }
}

// ---------------------------------------------------------------------------
// fp16 wmma GEMM (fp32 accum), BM=128 x BN tile, BK=32, NST-stage cp.async.
// 256 threads = 8 warps (4 M x 2 N); warp tile 32 x (BN/2).
//   out[m, j] = op( sum_k A[m,k] * W[j,k] + bias[j] ),  op chosen by j0<opSplit
// OutT: float (GEMM3) or __half (GEMM1 -> g_sh_h)
// ---------------------------------------------------------------------------
template <int BN, int NST, typename OutT>
__global__ __launch_bounds__(256) void gemm_f16_kernel(
    const __half* __restrict__ A, int lda,
    const __half* __restrict__ W, const float* __restrict__ bias,
    int op0, int op1, int opSplit, int K,
    OutT* __restrict__ out, int ldo)
{
    constexpr int NF  = BN / 32;
    constexpr int STG = (BM + BN) * PADH;
    __shared__ __half smem_all[NST * STG];

    const int m0 = blockIdx.x * BM;
    const int j0 = blockIdx.y * BN;
    const int op = (j0 < opSplit) ? op0 : op1;

    const int tid  = threadIdx.x;
    const int warp = tid >> 5;
    const int lane = tid & 31;
    const int wm = (warp & 3) * 32;
    const int wn = (warp >> 2) * (BN / 2);

    const int niters = K / BKG;

    auto issue_load = [&](int it, int buf) {
        __half* sa = smem_all + buf * STG;
        __half* sb = sa + BM * PADH;
        int kb = it * BKG;
        constexpr int NLD = 2 + BN / 64;
        #pragma unroll
        for (int i = 0; i < NLD; i++) {
            int idx = tid + i * 256;
            if (idx < 512) {
                int r  = idx >> 2;
                int c8 = (idx & 3) << 3;
                cp_async16(&sa[r * PADH + c8], &A[(size_t)(m0 + r) * lda + kb + c8]);
            } else {
                int j  = idx - 512;
                int r  = j >> 2;
                int c8 = (j & 3) << 3;
                cp_async16(&sb[r * PADH + c8], &W[(size_t)(j0 + r) * K + kb + c8]);
            }
        }
    };

    wmma::fragment<wmma::accumulator, 16, 16, 16, float> c[2][NF];
    #pragma unroll
    for (int i = 0; i < 2; i++)
        #pragma unroll
        for (int j = 0; j < NF; j++)
            wmma::fill_fragment(c[i][j], 0.0f);

    #pragma unroll
    for (int s = 0; s < NST - 1; s++) {
        if (s < niters) issue_load(s, s);
        cp_commit();
    }

    for (int it = 0; it < niters; it++) {
        if (it + NST - 1 < niters) issue_load(it + NST - 1, (it + NST - 1) % NST);
        cp_commit();
        cp_wait<NST - 1>();
        __syncthreads();

        __half* sa = smem_all + (it % NST) * STG;
        __half* sb = sa + BM * PADH;

        #pragma unroll
        for (int kk = 0; kk < BKG; kk += 16) {
            wmma::fragment<wmma::matrix_a, 16, 16, 16, __half, wmma::row_major> af[2];
            wmma::fragment<wmma::matrix_b, 16, 16, 16, __half, wmma::col_major> bf[NF];
            #pragma unroll
            for (int mf = 0; mf < 2; mf++)
                wmma::load_matrix_sync(af[mf], &sa[(wm + mf * 16) * PADH + kk], PADH);
            #pragma unroll
            for (int nf = 0; nf < NF; nf++)
                wmma::load_matrix_sync(bf[nf], &sb[(wn + nf * 16) * PADH + kk], PADH);
            #pragma unroll
            for (int mf = 0; mf < 2; mf++)
                #pragma unroll
                for (int nf = 0; nf < NF; nf++)
                    wmma::mma_sync(c[mf][nf], af[mf], bf[nf], c[mf][nf]);
        }
        __syncthreads();
    }

    // Epilogue: per-warp fp32 smem staging (32x16 at pitch 20), bias + op.
    float* stage = reinterpret_cast<float*>(smem_all) + warp * (32 * 20);
    #pragma unroll
    for (int nf = 0; nf < NF; nf++) {
        wmma::store_matrix_sync(stage,           c[0][nf], 20, wmma::mem_row_major);
        wmma::store_matrix_sync(stage + 16 * 20, c[1][nf], 20, wmma::mem_row_major);
        __syncwarp();
        #pragma unroll
        for (int i = 0; i < 4; i++) {
            int idx = lane + i * 32;     // 0..127
            int r   = idx >> 2;          // 0..31
            int c4  = (idx & 3) << 2;    // 0,4,8,12
            float4 v = *reinterpret_cast<float4*>(&stage[r * 20 + c4]);
            float vv[4] = {v.x, v.y, v.z, v.w};
            #pragma unroll
            for (int t = 0; t < 4; t++) {
                float x = vv[t] + bias[j0 + wn + nf * 16 + c4 + t];
                if (op == 1)      x = sigmoid_f(x);
                else if (op == 2) x = gelu_exact(x);
                vv[t] = x;
            }
            OutT* dst = &out[(size_t)(m0 + wm + r) * ldo + j0 + wn + nf * 16 + c4];
            if (sizeof(OutT) == 2) {
                __half2 h0 = __floats2half2_rn(vv[0], vv[1]);
                __half2 h1 = __floats2half2_rn(vv[2], vv[3]);
                uint2 u;
                u.x = *reinterpret_cast<unsigned*>(&h0);
                u.y = *reinterpret_cast<unsigned*>(&h1);
                *reinterpret_cast<uint2*>(dst) = u;
            } else {
                *reinterpret_cast<float4*>(dst) = make_float4(vv[0], vv[1], vv[2], vv[3]);
            }
        }
        __syncwarp();
    }
}

// ---------------------------------------------------------------------------
// Pass A: per-chunk sums. 256 threads: grp = tid>>7 picks rows 0-7 / 8-15,
// d = tid&127 owns channel pair (2d, 2d+1) via half2. smem-combine groups.
// ---------------------------------------------------------------------------
__global__ __launch_bounds__(256) void chunk_sum_kernel() {
    const int b   = blockIdx.x / NCHUNK;
    const int ch  = blockIdx.x % NCHUNK;
    const int d   = threadIdx.x & 127;
    const int grp = threadIdx.x >> 7;

    size_t base = ((size_t)(b * NN + ch * CHUNK + grp * 8)) * 1024;
    float2 lo = {0.f, 0.f}, hi = {0.f, 0.f};
    #pragma unroll
    for (int r = 0; r < 8; r++) {
        float2 f1 = __half22float2(*reinterpret_cast<const __half2*>(
                        &g_sh_h[base + (size_t)r * 1024 + 512 + 2 * d]));
        float2 f2 = __half22float2(*reinterpret_cast<const __half2*>(
                        &g_sh_h[base + (size_t)r * 1024 + 768 + 2 * d]));
        lo.x += f1.x;        lo.y += f1.y;
        hi.x += f1.x * f2.x; hi.y += f1.y * f2.y;
    }

    __shared__ float2 s_lo[128], s_hi[128];
    if (grp == 1) { s_lo[d] = lo; s_hi[d] = hi; }
    __syncthreads();
    if (grp == 0) {
        lo.x += s_lo[d].x; lo.y += s_lo[d].y;
        hi.x += s_hi[d].x; hi.y += s_hi[d].y;
        int pb = (b * NCHUNK + ch) * DE;
        *reinterpret_cast<float2*>(&g_part[pb + 2 * d])       = lo;
        *reinterpret_cast<float2*>(&g_part[pb + 256 + 2 * d]) = hi;
    }
}

// ---------------------------------------------------------------------------
// Block-parallel exclusive scan of chunk partials along the chunk axis.
// ---------------------------------------------------------------------------
__global__ __launch_bounds__(256) void scan_part_kernel() {
    const int b = blockIdx.x / DE;
    const int d = blockIdx.x % DE;
    const int c = threadIdx.x;          // 0..255 == NCHUNK
    const int lane = c & 31;
    const int wid  = c >> 5;

    int idx = (b * NCHUNK + c) * DE + d;
    float v = g_part[idx];

    float x = v;
    #pragma unroll
    for (int off = 1; off < 32; off <<= 1) {
        float y = __shfl_up_sync(0xFFFFFFFFu, x, off);
        if (lane >= off) x += y;
    }

    __shared__ float wsum[8];
    if (lane == 31) wsum[wid] = x;
    __syncthreads();

    __shared__ float woff[8];
    if (wid == 0 && lane < 8) {
        float t = wsum[lane];
        #pragma unroll
        for (int off = 1; off < 8; off <<= 1) {
            float y = __shfl_up_sync(0xFFu, t, off);
            if (lane >= off) t += y;
        }
        woff[lane] = t;
    }
    __syncthreads();

    float base = (wid == 0) ? 0.0f : woff[wid - 1];
    g_part[idx] = base + x - v;   // exclusive prefix
}

// ---------------------------------------------------------------------------
// Pass B: split-row register-buffered scan + gate + normalize -> fp16 g_o_h.
// grp 0 handles rows 0-7, grp 1 rows 8-15; grp 0 publishes its total via smem.
// ---------------------------------------------------------------------------
__global__ __launch_bounds__(256) void scan_apply_kernel() {
    const int b   = blockIdx.x / NCHUNK;
    const int ch  = blockIdx.x % NCHUNK;
    const int d   = threadIdx.x & 127;
    const int grp = threadIdx.x >> 7;

    size_t rowbase = ((size_t)(b * NN + ch * CHUNK + grp * 8)) * 1024;
    float2 clo[8], chi[8];
    float2 run_lo = {0.f, 0.f}, run_hi = {0.f, 0.f};
    #pragma unroll
    for (int r = 0; r < 8; r++) {
        float2 f1 = __half22float2(*reinterpret_cast<const __half2*>(
                        &g_sh_h[rowbase + (size_t)r * 1024 + 512 + 2 * d]));
        float2 f2 = __half22float2(*reinterpret_cast<const __half2*>(
                        &g_sh_h[rowbase + (size_t)r * 1024 + 768 + 2 * d]));
        run_lo.x += f1.x;        run_lo.y += f1.y;
        run_hi.x += f1.x * f2.x; run_hi.y += f1.y * f2.y;
        clo[r] = run_lo; chi[r] = run_hi;
    }

    __shared__ float2 s_lo[128], s_hi[128];
    if (grp == 0) { s_lo[d] = run_lo; s_hi[d] = run_hi; }
    __syncthreads();

    int pb = (b * NCHUNK + ch) * DE;
    float2 off_lo = *reinterpret_cast<const float2*>(&g_part[pb + 2 * d]);
    float2 off_hi = *reinterpret_cast<const float2*>(&g_part[pb + 256 + 2 * d]);
    if (grp == 1) {
        off_lo.x += s_lo[d].x; off_lo.y += s_lo[d].y;
        off_hi.x += s_hi[d].x; off_hi.y += s_hi[d].y;
    }

    #pragma unroll
    for (int r = 0; r < 8; r++) {
        int n = ch * CHUNK + grp * 8 + r;
        size_t row = (size_t)(b * NN + n);
        float rec = 1.0f / ((float)(n + 1) + 1e-7f);
        float2 G1 = __half22float2(*reinterpret_cast<const __half2*>(
                        &g_sh_h[row * 1024 + 2 * d]));
        float2 G2 = __half22float2(*reinterpret_cast<const __half2*>(
                        &g_sh_h[row * 1024 + 256 + 2 * d]));
        float o1x = G1.x * (off_lo.x + clo[r].x) * rec;
        float o1y = G1.y * (off_lo.y + clo[r].y) * rec;
        float o2x = G2.x * (off_hi.x + chi[r].x) * rec;
        float o2y = G2.y * (off_hi.y + chi[r].y) * rec;
        *reinterpret_cast<__half2*>(&g_o_h[row * DE + 2 * d])       = __floats2half2_rn(o1x, o1y);
        *reinterpret_cast<__half2*>(&g_o_h[row * DE + 256 + 2 * d]) = __floats2half2_rn(o2x, o2y);
    }
}

// ---------------------------------------------------------------------------
// Launcher
// ---------------------------------------------------------------------------
extern "C" void kernel_launch(void* const* d_in, const int* in_sizes, int n_in,
                              void* d_out, int out_size) {
    const float* xq   = (const float*)d_in[0];
    const float* W_se = (const float*)d_in[2];
    const float* b_se = (const float*)d_in[3];
    const float* W_po = (const float*)d_in[4];
    const float* b_po = (const float*)d_in[5];
    const float* W_ag = (const float*)d_in[6];
    const float* b_ag = (const float*)d_in[7];
    float* out = (float*)d_out;

    __half* shh_ptr = nullptr;
    __half* oh_ptr  = nullptr;
    __half* xqh_ptr = nullptr;
    __half* w1_ptr  = nullptr;
    __half* w3_ptr  = nullptr;
    float*  b1_ptr  = nullptr;
    cudaGetSymbolAddress((void**)&shh_ptr, g_sh_h);
    cudaGetSymbolAddress((void**)&oh_ptr,  g_o_h);
    cudaGetSymbolAddress((void**)&xqh_ptr, g_xq_h);
    cudaGetSymbolAddress((void**)&w1_ptr,  g_w1_h);
    cudaGetSymbolAddress((void**)&w3_ptr,  g_w3_h);
    cudaGetSymbolAddress((void**)&b1_ptr,  g_b1);

    // fp16 conversions (one launch)
    conv_all_kernel<<<(TOT * DIMV) / 1024, 256>>>(xq, W_se, W_po, W_ag, b_se, b_po);

    // GEMM1+2 fused: [16384,128] x [1024,128]^T -> gate | gelu(h), fp16 out
    {
        dim3 grid(TOT / BM, 1024 / 128);   // (128, 8)
        gemm_f16_kernel<128, 2, __half><<<grid, 256>>>(
            xqh_ptr, DIMV,
            w1_ptr, b1_ptr,
            /*op0=*/1, /*op1=*/2, /*opSplit=*/DE, /*K=*/DIMV,
            shh_ptr, /*ldo=*/1024);
    }

    chunk_sum_kernel<<<BB * NCHUNK, 256>>>();
    scan_part_kernel<<<BB * DE, 256>>>();
    scan_apply_kernel<<<BB * NCHUNK, 256>>>();

    // GEMM3: [16384,512] x [128,512]^T -> out (fp32)
    {
        dim3 grid(TOT / BM, DIMV / 64);    // (128, 2)
        gemm_f16_kernel<64, 3, float><<<grid, 256>>>(
            oh_ptr, DE,
            w3_ptr, b_ag,
            /*op0=*/0, /*op1=*/0, /*opSplit=*/1 << 30, /*K=*/DE,
            out, /*ldo=*/DIMV);
    }
}

// round 12
// speedup vs baseline: 3.9263x; 1.0203x over previous
#include <cuda_runtime.h>
#include <cuda_fp16.h>
#include <mma.h>
#include <cstdint>

using namespace nvcuda;

#define BB 4
#define NN 4096
#define DIMV 128
#define DE 512
#define TOT (BB * NN)          // 16384 rows
#define CHUNK 16
#define NCHUNK (NN / CHUNK)    // 256

// Scratch (allocation-free: __device__ globals)
// g_sh_h per row (fp16): [0,512) = sigmoid(s) gate, [512,1024) = gelu(h)
__device__ __half g_sh_h[(size_t)TOT * 1024];
__device__ __half g_o_h[(size_t)TOT * DE];    // gated aggregation (fp16), input to GEMM3
// g_part layout: [b][d][c]  (d-major; c contiguous) -> coalesced warp scans
__device__ float  g_part[BB * DE * NCHUNK];
__device__ __half g_xq_h[(size_t)TOT * DIMV]; // fp16 copy of xq
__device__ __half g_w1_h[1024 * DIMV];        // [W_se; W_po] fp16
__device__ __half g_w3_h[DIMV * DE];          // W_ag fp16
__device__ float  g_b1[1024];                 // [b_se; b_po]

#define BM 128
#define BKG 32
#define PADH 40                 // half pitch: 80 B, multiple of 16

__device__ __forceinline__ float gelu_exact(float x) {
    return 0.5f * x * (1.0f + erff(x * 0.70710678118654752f));
}
__device__ __forceinline__ float sigmoid_f(float x) {
    return 1.0f / (1.0f + expf(-x));
}

__device__ __forceinline__ void cp_async16(void* smem_dst, const void* gmem_src) {
    unsigned s = (unsigned)__cvta_generic_to_shared(smem_dst);
    asm volatile("cp.async.cg.shared.global [%0], [%1], 16;" :: "r"(s), "l"(gmem_src));
}
__device__ __forceinline__ void cp_commit() {
    asm volatile("cp.async.commit_group;");
}
template <int N>
__device__ __forceinline__ void cp_wait() {
    asm volatile("cp.async.wait_group %0;" :: "n"(N));
}

// ---------------------------------------------------------------------------
// Merged conversion kernel (one launch)
// ---------------------------------------------------------------------------
__global__ __launch_bounds__(256) void conv_all_kernel(
    const float* __restrict__ x,
    const float* __restrict__ wse, const float* __restrict__ wpo,
    const float* __restrict__ wag,
    const float* __restrict__ bse, const float* __restrict__ bpo)
{
    int i = blockIdx.x * 256 + threadIdx.x;    // grid: 2048*256 = 524288
    {   // xq: 2,097,152 elems = 524,288 float4 slots
        int e = i * 4;
        float4 v = *reinterpret_cast<const float4*>(&x[e]);
        *reinterpret_cast<__half2*>(&g_xq_h[e])     = __floats2half2_rn(v.x, v.y);
        *reinterpret_cast<__half2*>(&g_xq_h[e + 2]) = __floats2half2_rn(v.z, v.w);
    }
    if (i < 65536) {
        g_w1_h[i]         = __float2half(wse[i]);
        g_w1_h[65536 + i] = __float2half(wpo[i]);
        g_w3_h[i]         = __float2half(wag[i]);
        if (i < 512) { g_b1[i] = bse[i]; g_b1[512 + i] = bpo[i]; }
    }
}

// ---------------------------------------------------------------------------
// fp16 wmma GEMM (fp32 accum), BM=128 x BN tile, BK=32, NST-stage cp.async.
// 256 threads = 8 warps (4 M x 2 N); warp tile 32 x (BN/2).
//   out[m, j] = op( sum_k A[m,k] * W[j,k] + bias[j] ),  op chosen by j0<opSplit
// OutT: float (GEMM3) or __half (GEMM1 -> g_sh_h)
// ---------------------------------------------------------------------------
template <int BN, int NST, typename OutT>
__global__ __launch_bounds__(256) void gemm_f16_kernel(
    const __half* __restrict__ A, int lda,
    const __half* __restrict__ W, const float* __restrict__ bias,
    int op0, int op1, int opSplit, int K,
    OutT* __restrict__ out, int ldo)
{
    constexpr int NF  = BN / 32;
    constexpr int STG = (BM + BN) * PADH;
    __shared__ __half smem_all[NST * STG];

    const int m0 = blockIdx.x * BM;
    const int j0 = blockIdx.y * BN;
    const int op = (j0 < opSplit) ? op0 : op1;

    const int tid  = threadIdx.x;
    const int warp = tid >> 5;
    const int lane = tid & 31;
    const int wm = (warp & 3) * 32;
    const int wn = (warp >> 2) * (BN / 2);

    const int niters = K / BKG;

    auto issue_load = [&](int it, int buf) {
        __half* sa = smem_all + buf * STG;
        __half* sb = sa + BM * PADH;
        int kb = it * BKG;
        constexpr int NLD = 2 + BN / 64;
        #pragma unroll
        for (int i = 0; i < NLD; i++) {
            int idx = tid + i * 256;
            if (idx < 512) {
                int r  = idx >> 2;
                int c8 = (idx & 3) << 3;
                cp_async16(&sa[r * PADH + c8], &A[(size_t)(m0 + r) * lda + kb + c8]);
            } else {
                int j  = idx - 512;
                int r  = j >> 2;
                int c8 = (j & 3) << 3;
                cp_async16(&sb[r * PADH + c8], &W[(size_t)(j0 + r) * K + kb + c8]);
            }
        }
    };

    wmma::fragment<wmma::accumulator, 16, 16, 16, float> c[2][NF];
    #pragma unroll
    for (int i = 0; i < 2; i++)
        #pragma unroll
        for (int j = 0; j < NF; j++)
            wmma::fill_fragment(c[i][j], 0.0f);

    #pragma unroll
    for (int s = 0; s < NST - 1; s++) {
        if (s < niters) issue_load(s, s);
        cp_commit();
    }

    for (int it = 0; it < niters; it++) {
        if (it + NST - 1 < niters) issue_load(it + NST - 1, (it + NST - 1) % NST);
        cp_commit();
        cp_wait<NST - 1>();
        __syncthreads();

        __half* sa = smem_all + (it % NST) * STG;
        __half* sb = sa + BM * PADH;

        #pragma unroll
        for (int kk = 0; kk < BKG; kk += 16) {
            wmma::fragment<wmma::matrix_a, 16, 16, 16, __half, wmma::row_major> af[2];
            wmma::fragment<wmma::matrix_b, 16, 16, 16, __half, wmma::col_major> bf[NF];
            #pragma unroll
            for (int mf = 0; mf < 2; mf++)
                wmma::load_matrix_sync(af[mf], &sa[(wm + mf * 16) * PADH + kk], PADH);
            #pragma unroll
            for (int nf = 0; nf < NF; nf++)
                wmma::load_matrix_sync(bf[nf], &sb[(wn + nf * 16) * PADH + kk], PADH);
            #pragma unroll
            for (int mf = 0; mf < 2; mf++)
                #pragma unroll
                for (int nf = 0; nf < NF; nf++)
                    wmma::mma_sync(c[mf][nf], af[mf], bf[nf], c[mf][nf]);
        }
        __syncthreads();
    }

    // Epilogue: per-warp fp32 smem staging (32x16 at pitch 20), bias + op.
    float* stage = reinterpret_cast<float*>(smem_all) + warp * (32 * 20);
    #pragma unroll
    for (int nf = 0; nf < NF; nf++) {
        wmma::store_matrix_sync(stage,           c[0][nf], 20, wmma::mem_row_major);
        wmma::store_matrix_sync(stage + 16 * 20, c[1][nf], 20, wmma::mem_row_major);
        __syncwarp();
        #pragma unroll
        for (int i = 0; i < 4; i++) {
            int idx = lane + i * 32;     // 0..127
            int r   = idx >> 2;          // 0..31
            int c4  = (idx & 3) << 2;    // 0,4,8,12
            float4 v = *reinterpret_cast<float4*>(&stage[r * 20 + c4]);
            float vv[4] = {v.x, v.y, v.z, v.w};
            #pragma unroll
            for (int t = 0; t < 4; t++) {
                float x = vv[t] + bias[j0 + wn + nf * 16 + c4 + t];
                if (op == 1)      x = sigmoid_f(x);
                else if (op == 2) x = gelu_exact(x);
                vv[t] = x;
            }
            OutT* dst = &out[(size_t)(m0 + wm + r) * ldo + j0 + wn + nf * 16 + c4];
            if (sizeof(OutT) == 2) {
                __half2 h0 = __floats2half2_rn(vv[0], vv[1]);
                __half2 h1 = __floats2half2_rn(vv[2], vv[3]);
                uint2 u;
                u.x = *reinterpret_cast<unsigned*>(&h0);
                u.y = *reinterpret_cast<unsigned*>(&h1);
                *reinterpret_cast<uint2*>(dst) = u;
            } else {
                *reinterpret_cast<float4*>(dst) = make_float4(vv[0], vv[1], vv[2], vv[3]);
            }
        }
        __syncwarp();
    }
}

// ---------------------------------------------------------------------------
// Pass A: per-chunk sums. 256 threads: grp = tid>>7 picks rows 0-7 / 8-15,
// d = tid&127 owns channel pair (2d, 2d+1) via half2. smem-combine groups.
// Writes d-major g_part[b][channel][ch].
// ---------------------------------------------------------------------------
__global__ __launch_bounds__(256) void chunk_sum_kernel() {
    const int b   = blockIdx.x / NCHUNK;
    const int ch  = blockIdx.x % NCHUNK;
    const int d   = threadIdx.x & 127;
    const int grp = threadIdx.x >> 7;

    size_t base = ((size_t)(b * NN + ch * CHUNK + grp * 8)) * 1024;
    float2 lo = {0.f, 0.f}, hi = {0.f, 0.f};
    #pragma unroll
    for (int r = 0; r < 8; r++) {
        float2 f1 = __half22float2(*reinterpret_cast<const __half2*>(
                        &g_sh_h[base + (size_t)r * 1024 + 512 + 2 * d]));
        float2 f2 = __half22float2(*reinterpret_cast<const __half2*>(
                        &g_sh_h[base + (size_t)r * 1024 + 768 + 2 * d]));
        lo.x += f1.x;        lo.y += f1.y;
        hi.x += f1.x * f2.x; hi.y += f1.y * f2.y;
    }

    __shared__ float2 s_lo[128], s_hi[128];
    if (grp == 1) { s_lo[d] = lo; s_hi[d] = hi; }
    __syncthreads();
    if (grp == 0) {
        lo.x += s_lo[d].x; lo.y += s_lo[d].y;
        hi.x += s_hi[d].x; hi.y += s_hi[d].y;
        size_t pb = (size_t)b * DE * NCHUNK + ch;
        g_part[pb + (size_t)(2 * d)       * NCHUNK] = lo.x;
        g_part[pb + (size_t)(2 * d + 1)   * NCHUNK] = lo.y;
        g_part[pb + (size_t)(256 + 2 * d) * NCHUNK] = hi.x;
        g_part[pb + (size_t)(257 + 2 * d) * NCHUNK] = hi.y;
    }
}

// ---------------------------------------------------------------------------
// Exclusive scan along c for each (b,d): one warp per (b,d), fully coalesced
// (c is contiguous). 8 segments of 32, shuffle scan with carry, in-place.
// ---------------------------------------------------------------------------
__global__ __launch_bounds__(256) void scan_part_kernel() {
    const int w    = (blockIdx.x * 256 + threadIdx.x) >> 5;  // 0..2047 = (b,d)
    const int lane = threadIdx.x & 31;
    size_t base = (size_t)w * NCHUNK;

    float carry = 0.0f;
    #pragma unroll
    for (int seg = 0; seg < 8; seg++) {
        float v = g_part[base + seg * 32 + lane];
        float x = v;
        #pragma unroll
        for (int off = 1; off < 32; off <<= 1) {
            float y = __shfl_up_sync(0xFFFFFFFFu, x, off);
            if (lane >= off) x += y;
        }
        g_part[base + seg * 32 + lane] = carry + x - v;   // exclusive
        carry += __shfl_sync(0xFFFFFFFFu, x, 31);
    }
}

// ---------------------------------------------------------------------------
// Pass B: split-row register-buffered scan + gate + normalize -> fp16 g_o_h.
// grp 0 handles rows 0-7, grp 1 rows 8-15; grp 0 publishes its total via smem.
// Reads d-major g_part offsets (4 scalar loads per thread, once per block).
// ---------------------------------------------------------------------------
__global__ __launch_bounds__(256) void scan_apply_kernel() {
    const int b   = blockIdx.x / NCHUNK;
    const int ch  = blockIdx.x % NCHUNK;
    const int d   = threadIdx.x & 127;
    const int grp = threadIdx.x >> 7;

    // Issue offset loads early (independent of the row loop).
    size_t pb = (size_t)b * DE * NCHUNK + ch;
    float2 off_lo, off_hi;
    off_lo.x = g_part[pb + (size_t)(2 * d)       * NCHUNK];
    off_lo.y = g_part[pb + (size_t)(2 * d + 1)   * NCHUNK];
    off_hi.x = g_part[pb + (size_t)(256 + 2 * d) * NCHUNK];
    off_hi.y = g_part[pb + (size_t)(257 + 2 * d) * NCHUNK];

    size_t rowbase = ((size_t)(b * NN + ch * CHUNK + grp * 8)) * 1024;
    float2 clo[8], chi[8];
    float2 run_lo = {0.f, 0.f}, run_hi = {0.f, 0.f};
    #pragma unroll
    for (int r = 0; r < 8; r++) {
        float2 f1 = __half22float2(*reinterpret_cast<const __half2*>(
                        &g_sh_h[rowbase + (size_t)r * 1024 + 512 + 2 * d]));
        float2 f2 = __half22float2(*reinterpret_cast<const __half2*>(
                        &g_sh_h[rowbase + (size_t)r * 1024 + 768 + 2 * d]));
        run_lo.x += f1.x;        run_lo.y += f1.y;
        run_hi.x += f1.x * f2.x; run_hi.y += f1.y * f2.y;
        clo[r] = run_lo; chi[r] = run_hi;
    }

    __shared__ float2 s_lo[128], s_hi[128];
    if (grp == 0) { s_lo[d] = run_lo; s_hi[d] = run_hi; }
    __syncthreads();

    if (grp == 1) {
        off_lo.x += s_lo[d].x; off_lo.y += s_lo[d].y;
        off_hi.x += s_hi[d].x; off_hi.y += s_hi[d].y;
    }

    #pragma unroll
    for (int r = 0; r < 8; r++) {
        int n = ch * CHUNK + grp * 8 + r;
        size_t row = (size_t)(b * NN + n);
        float rec = 1.0f / ((float)(n + 1) + 1e-7f);
        float2 G1 = __half22float2(*reinterpret_cast<const __half2*>(
                        &g_sh_h[row * 1024 + 2 * d]));
        float2 G2 = __half22float2(*reinterpret_cast<const __half2*>(
                        &g_sh_h[row * 1024 + 256 + 2 * d]));
        float o1x = G1.x * (off_lo.x + clo[r].x) * rec;
        float o1y = G1.y * (off_lo.y + clo[r].y) * rec;
        float o2x = G2.x * (off_hi.x + chi[r].x) * rec;
        float o2y = G2.y * (off_hi.y + chi[r].y) * rec;
        *reinterpret_cast<__half2*>(&g_o_h[row * DE + 2 * d])       = __floats2half2_rn(o1x, o1y);
        *reinterpret_cast<__half2*>(&g_o_h[row * DE + 256 + 2 * d]) = __floats2half2_rn(o2x, o2y);
    }
}

// ---------------------------------------------------------------------------
// Launcher
// ---------------------------------------------------------------------------
extern "C" void kernel_launch(void* const* d_in, const int* in_sizes, int n_in,
                              void* d_out, int out_size) {
    const float* xq   = (const float*)d_in[0];
    const float* W_se = (const float*)d_in[2];
    const float* b_se = (const float*)d_in[3];
    const float* W_po = (const float*)d_in[4];
    const float* b_po = (const float*)d_in[5];
    const float* W_ag = (const float*)d_in[6];
    const float* b_ag = (const float*)d_in[7];
    float* out = (float*)d_out;

    __half* shh_ptr = nullptr;
    __half* oh_ptr  = nullptr;
    __half* xqh_ptr = nullptr;
    __half* w1_ptr  = nullptr;
    __half* w3_ptr  = nullptr;
    float*  b1_ptr  = nullptr;
    cudaGetSymbolAddress((void**)&shh_ptr, g_sh_h);
    cudaGetSymbolAddress((void**)&oh_ptr,  g_o_h);
    cudaGetSymbolAddress((void**)&xqh_ptr, g_xq_h);
    cudaGetSymbolAddress((void**)&w1_ptr,  g_w1_h);
    cudaGetSymbolAddress((void**)&w3_ptr,  g_w3_h);
    cudaGetSymbolAddress((void**)&b1_ptr,  g_b1);

    // fp16 conversions (one launch)
    conv_all_kernel<<<(TOT * DIMV) / 1024, 256>>>(xq, W_se, W_po, W_ag, b_se, b_po);

    // GEMM1+2 fused: [16384,128] x [1024,128]^T -> gate | gelu(h), fp16 out
    {
        dim3 grid(TOT / BM, 1024 / 128);   // (128, 8)
        gemm_f16_kernel<128, 2, __half><<<grid, 256>>>(
            xqh_ptr, DIMV,
            w1_ptr, b1_ptr,
            /*op0=*/1, /*op1=*/2, /*opSplit=*/DE, /*K=*/DIMV,
            shh_ptr, /*ldo=*/1024);
    }

    chunk_sum_kernel<<<BB * NCHUNK, 256>>>();
    scan_part_kernel<<<(BB * DE * 32) / 256, 256>>>();   // 256 blocks, warp/(b,d)
    scan_apply_kernel<<<BB * NCHUNK, 256>>>();

    // GEMM3: [16384,512] x [128,512]^T -> out (fp32)
    {
        dim3 grid(TOT / BM, DIMV / 64);    // (128, 2)
        gemm_f16_kernel<64, 3, float><<<grid, 256>>>(
            oh_ptr, DE,
            w3_ptr, b_ag,
            /*op0=*/0, /*op1=*/0, /*opSplit=*/1 << 30, /*K=*/DE,
            out, /*ldo=*/DIMV);
    }
}

// round 13
// speedup vs baseline: 4.5916x; 1.1695x over previous
#include <cuda_runtime.h>
#include <cuda_fp16.h>
#include <mma.h>
#include <cstdint>

using namespace nvcuda;

#define BB 4
#define NN 4096
#define DIMV 128
#define DE 512
#define TOT (BB * NN)          // 16384 rows
#define CHUNK 16
#define NCHUNK (NN / CHUNK)    // 256

// Scratch (allocation-free: __device__ globals)
// Channel permutation: p=2d <-> orig d (lo), p=2d+1 <-> orig d+256 (hi).
// g_sh_h per row (fp16): [0,512) = sigmoid(s) gate (perm), [512,1024) = combined
//   where combined[2d] = gelu(h_d), combined[2d+1] = gelu(h_d)*gelu(h_{d+256}).
__device__ __half g_sh_h[(size_t)TOT * 1024];
__device__ __half g_o_h[(size_t)TOT * DE];    // gated aggregation (fp16, perm order)
// g_part layout: [b][p][c]  (p-major; c contiguous)
__device__ float  g_part[BB * DE * NCHUNK];
__device__ __half g_xq_h[(size_t)TOT * DIMV]; // fp16 copy of xq
__device__ __half g_w1_h[1024 * DIMV];        // [W_se; W_po] fp16, rows permuted
__device__ __half g_w3_h[DIMV * DE];          // W_ag fp16, K-dim permuted
__device__ float  g_b1[1024];                 // [b_se; b_po] permuted

#define BM 128
#define BKG 32
#define PADH 40                 // half pitch: 80 B, multiple of 16

__device__ __forceinline__ float gelu_exact(float x) {
    return 0.5f * x * (1.0f + erff(x * 0.70710678118654752f));
}
__device__ __forceinline__ float sigmoid_f(float x) {
    return 1.0f / (1.0f + expf(-x));
}
__device__ __forceinline__ int perm_orig(int p) {     // permuted -> original channel
    return (p & 1) ? 256 + (p >> 1) : (p >> 1);
}

__device__ __forceinline__ void cp_async16(void* smem_dst, const void* gmem_src) {
    unsigned s = (unsigned)__cvta_generic_to_shared(smem_dst);
    asm volatile("cp.async.cg.shared.global [%0], [%1], 16;" :: "r"(s), "l"(gmem_src));
}
__device__ __forceinline__ void cp_commit() {
    asm volatile("cp.async.commit_group;");
}
template <int N>
__device__ __forceinline__ void cp_wait() {
    asm volatile("cp.async.wait_group %0;" :: "n"(N));
}

// ---------------------------------------------------------------------------
// Merged conversion kernel (one launch) — applies the channel permutation.
// ---------------------------------------------------------------------------
__global__ __launch_bounds__(256) void conv_all_kernel(
    const float* __restrict__ x,
    const float* __restrict__ wse, const float* __restrict__ wpo,
    const float* __restrict__ wag,
    const float* __restrict__ bse, const float* __restrict__ bpo)
{
    int i = blockIdx.x * 256 + threadIdx.x;    // grid: 2048*256 = 524288
    {   // xq: 2,097,152 elems = 524,288 float4 slots
        int e = i * 4;
        float4 v = *reinterpret_cast<const float4*>(&x[e]);
        *reinterpret_cast<__half2*>(&g_xq_h[e])     = __floats2half2_rn(v.x, v.y);
        *reinterpret_cast<__half2*>(&g_xq_h[e + 2]) = __floats2half2_rn(v.z, v.w);
    }
    if (i < 65536) {
        {   // W_se / W_po: permuted rows. i = r*128 + k
            int r = i >> 7, k = i & 127;
            int po = perm_orig(r);
            g_w1_h[i]         = __float2half(wse[po * 128 + k]);
            g_w1_h[65536 + i] = __float2half(wpo[po * 128 + k]);
        }
        {   // W_ag: permuted K. i = j*512 + p
            int j = i >> 9, p = i & 511;
            g_w3_h[i] = __float2half(wag[j * 512 + perm_orig(p)]);
        }
        if (i < 512) {
            int po = perm_orig(i);
            g_b1[i] = bse[po]; g_b1[512 + i] = bpo[po];
        }
    }
}

// ---------------------------------------------------------------------------
// fp16 wmma GEMM (fp32 accum), BM=128 x BN tile, BK=32, NST-stage cp.async.
// 256 threads = 8 warps (4 M x 2 N); warp tile 32 x (BN/2).
// op: 0=none 1=sigmoid 2=gelu+pair-combine (+ fused per-chunk column sums
//     into g_part — each (chunk,p) owned by exactly one warp).
// ---------------------------------------------------------------------------
template <int BN, int NST, typename OutT>
__global__ __launch_bounds__(256) void gemm_f16_kernel(
    const __half* __restrict__ A, int lda,
    const __half* __restrict__ W, const float* __restrict__ bias,
    int op0, int op1, int opSplit, int K,
    OutT* __restrict__ out, int ldo)
{
    constexpr int NF  = BN / 32;
    constexpr int STG = (BM + BN) * PADH;
    __shared__ __half smem_all[NST * STG];

    const int m0 = blockIdx.x * BM;
    const int j0 = blockIdx.y * BN;
    const int op = (j0 < opSplit) ? op0 : op1;

    const int tid  = threadIdx.x;
    const int warp = tid >> 5;
    const int lane = tid & 31;
    const int wm = (warp & 3) * 32;
    const int wn = (warp >> 2) * (BN / 2);

    const int niters = K / BKG;

    auto issue_load = [&](int it, int buf) {
        __half* sa = smem_all + buf * STG;
        __half* sb = sa + BM * PADH;
        int kb = it * BKG;
        constexpr int NLD = 2 + BN / 64;
        #pragma unroll
        for (int i = 0; i < NLD; i++) {
            int idx = tid + i * 256;
            if (idx < 512) {
                int r  = idx >> 2;
                int c8 = (idx & 3) << 3;
                cp_async16(&sa[r * PADH + c8], &A[(size_t)(m0 + r) * lda + kb + c8]);
            } else {
                int j  = idx - 512;
                int r  = j >> 2;
                int c8 = (j & 3) << 3;
                cp_async16(&sb[r * PADH + c8], &W[(size_t)(j0 + r) * K + kb + c8]);
            }
        }
    };

    wmma::fragment<wmma::accumulator, 16, 16, 16, float> c[2][NF];
    #pragma unroll
    for (int i = 0; i < 2; i++)
        #pragma unroll
        for (int j = 0; j < NF; j++)
            wmma::fill_fragment(c[i][j], 0.0f);

    #pragma unroll
    for (int s = 0; s < NST - 1; s++) {
        if (s < niters) issue_load(s, s);
        cp_commit();
    }

    for (int it = 0; it < niters; it++) {
        if (it + NST - 1 < niters) issue_load(it + NST - 1, (it + NST - 1) % NST);
        cp_commit();
        cp_wait<NST - 1>();
        __syncthreads();

        __half* sa = smem_all + (it % NST) * STG;
        __half* sb = sa + BM * PADH;

        #pragma unroll
        for (int kk = 0; kk < BKG; kk += 16) {
            wmma::fragment<wmma::matrix_a, 16, 16, 16, __half, wmma::row_major> af[2];
            wmma::fragment<wmma::matrix_b, 16, 16, 16, __half, wmma::col_major> bf[NF];
            #pragma unroll
            for (int mf = 0; mf < 2; mf++)
                wmma::load_matrix_sync(af[mf], &sa[(wm + mf * 16) * PADH + kk], PADH);
            #pragma unroll
            for (int nf = 0; nf < NF; nf++)
                wmma::load_matrix_sync(bf[nf], &sb[(wn + nf * 16) * PADH + kk], PADH);
            #pragma unroll
            for (int mf = 0; mf < 2; mf++)
                #pragma unroll
                for (int nf = 0; nf < NF; nf++)
                    wmma::mma_sync(c[mf][nf], af[mf], bf[nf], c[mf][nf]);
        }
        __syncthreads();
    }

    // Epilogue. Thread quad geometry: rows r = (lane>>2)+8i, col c4=(lane&3)*4.
    const int c4 = (lane & 3) << 2;
    const int bb = m0 >> 12;                 // batch (NN=4096, BM=128 divides)
    const int chA = ((m0 & (NN - 1)) + wm) >> 4;   // first chunk of warp tile
    float* stage = reinterpret_cast<float*>(smem_all) + warp * (32 * 20);

    #pragma unroll
    for (int nf = 0; nf < NF; nf++) {
        wmma::store_matrix_sync(stage,           c[0][nf], 20, wmma::mem_row_major);
        wmma::store_matrix_sync(stage + 16 * 20, c[1][nf], 20, wmma::mem_row_major);
        __syncwarp();
        float vv4[4][4];
        #pragma unroll
        for (int i = 0; i < 4; i++) {
            int r = (lane >> 2) + 8 * i;     // 0..31
            float4 v = *reinterpret_cast<float4*>(&stage[r * 20 + c4]);
            float* vv = vv4[i];
            vv[0] = v.x; vv[1] = v.y; vv[2] = v.z; vv[3] = v.w;
            #pragma unroll
            for (int t = 0; t < 4; t++)
                vv[t] += bias[j0 + wn + nf * 16 + c4 + t];
            if (op == 1) {
                #pragma unroll
                for (int t = 0; t < 4; t++) vv[t] = sigmoid_f(vv[t]);
            } else if (op == 2) {
                float e0 = gelu_exact(vv[0]), e1 = gelu_exact(vv[1]);
                float e2 = gelu_exact(vv[2]), e3 = gelu_exact(vv[3]);
                vv[0] = e0; vv[1] = e0 * e1;   // (lo, lo*hi) pairs
                vv[2] = e2; vv[3] = e2 * e3;
            }
            OutT* dst = &out[(size_t)(m0 + wm + r) * ldo + j0 + wn + nf * 16 + c4];
            if (sizeof(OutT) == 2) {
                __half2 h0 = __floats2half2_rn(vv[0], vv[1]);
                __half2 h1 = __floats2half2_rn(vv[2], vv[3]);
                uint2 u;
                u.x = *reinterpret_cast<unsigned*>(&h0);
                u.y = *reinterpret_cast<unsigned*>(&h1);
                *reinterpret_cast<uint2*>(dst) = u;
            } else {
                *reinterpret_cast<float4*>(dst) = make_float4(vv[0], vv[1], vv[2], vv[3]);
            }
        }
        if (op == 2) {
            // Per-chunk column sums: chunkA = rows i=0,1; chunkB = rows i=2,3.
            float sA[4], sB[4];
            #pragma unroll
            for (int t = 0; t < 4; t++) {
                sA[t] = vv4[0][t] + vv4[1][t];
                sB[t] = vv4[2][t] + vv4[3][t];
            }
            #pragma unroll
            for (int mk = 4; mk <= 16; mk <<= 1) {
                #pragma unroll
                for (int t = 0; t < 4; t++) {
                    sA[t] += __shfl_xor_sync(0xFFFFFFFFu, sA[t], mk);
                    sB[t] += __shfl_xor_sync(0xFFFFFFFFu, sB[t], mk);
                }
            }
            if ((lane >> 2) == 0) {          // lanes 0..3 hold full 16-row sums
                int p0 = (j0 - 512) + wn + nf * 16 + c4;
                #pragma unroll
                for (int t = 0; t < 4; t++) {
                    size_t gp = ((size_t)bb * DE + p0 + t) * NCHUNK;
                    g_part[gp + chA]     = sA[t];
                    g_part[gp + chA + 1] = sB[t];
                }
            }
        }
        __syncwarp();
    }
}

// ---------------------------------------------------------------------------
// Exclusive scan along c for each (b,p): one warp per (b,p), coalesced.
// All 8 segment loads hoisted (independent) -> MLP 8; serial carry only.
// ---------------------------------------------------------------------------
__global__ __launch_bounds__(256) void scan_part_kernel() {
    const int w    = (blockIdx.x * 256 + threadIdx.x) >> 5;  // 0..2047 = (b,p)
    const int lane = threadIdx.x & 31;
    size_t base = (size_t)w * NCHUNK;

    float v[8];
    #pragma unroll
    for (int seg = 0; seg < 8; seg++)
        v[seg] = g_part[base + seg * 32 + lane];

    float carry = 0.0f;
    #pragma unroll
    for (int seg = 0; seg < 8; seg++) {
        float x = v[seg];
        #pragma unroll
        for (int off = 1; off < 32; off <<= 1) {
            float y = __shfl_up_sync(0xFFFFFFFFu, x, off);
            if (lane >= off) x += y;
        }
        g_part[base + seg * 32 + lane] = carry + x - v[seg];   // exclusive
        carry += __shfl_sync(0xFFFFFFFFu, x, 31);
    }
}

// ---------------------------------------------------------------------------
// Pass B: linear (permuted) scan + gate + normalize -> fp16 g_o_h.
// Thread d handles channels 4d..4d+3; grp 0 rows 0-7, grp 1 rows 8-15.
// ---------------------------------------------------------------------------
__global__ __launch_bounds__(256) void scan_apply_kernel() {
    const int b   = blockIdx.x / NCHUNK;
    const int ch  = blockIdx.x % NCHUNK;
    const int d   = threadIdx.x & 127;   // channel group: p = 4d..4d+3
    const int grp = threadIdx.x >> 7;

    // Offsets (exclusive chunk prefix), 4 scalar loads, issued early.
    size_t pb = ((size_t)b * DE + 4 * d) * NCHUNK + ch;
    float4 off;
    off.x = g_part[pb];
    off.y = g_part[pb + NCHUNK];
    off.z = g_part[pb + 2 * (size_t)NCHUNK];
    off.w = g_part[pb + 3 * (size_t)NCHUNK];

    size_t rowbase = ((size_t)(b * NN + ch * CHUNK + grp * 8)) * 1024;
    float4 cum[8];
    float4 run = {0.f, 0.f, 0.f, 0.f};
    #pragma unroll
    for (int r = 0; r < 8; r++) {
        uint2 u = *reinterpret_cast<const uint2*>(&g_sh_h[rowbase + (size_t)r * 1024 + 512 + 4 * d]);
        float2 f0 = __half22float2(*reinterpret_cast<__half2*>(&u.x));
        float2 f1 = __half22float2(*reinterpret_cast<__half2*>(&u.y));
        run.x += f0.x; run.y += f0.y; run.z += f1.x; run.w += f1.y;
        cum[r] = run;
    }

    __shared__ float4 s_tot[128];
    if (grp == 0) s_tot[d] = run;
    __syncthreads();
    if (grp == 1) {
        float4 t = s_tot[d];
        off.x += t.x; off.y += t.y; off.z += t.z; off.w += t.w;
    }

    #pragma unroll
    for (int r = 0; r < 8; r++) {
        int n = ch * CHUNK + grp * 8 + r;
        size_t row = (size_t)(b * NN + n);
        float rec = 1.0f / ((float)(n + 1) + 1e-7f);
        uint2 ug = *reinterpret_cast<const uint2*>(&g_sh_h[row * 1024 + 4 * d]);
        float2 G0 = __half22float2(*reinterpret_cast<__half2*>(&ug.x));
        float2 G1 = __half22float2(*reinterpret_cast<__half2*>(&ug.y));
        float o0 = G0.x * (off.x + cum[r].x) * rec;
        float o1 = G0.y * (off.y + cum[r].y) * rec;
        float o2 = G1.x * (off.z + cum[r].z) * rec;
        float o3 = G1.y * (off.w + cum[r].w) * rec;
        __half2 h0 = __floats2half2_rn(o0, o1);
        __half2 h1 = __floats2half2_rn(o2, o3);
        uint2 uo;
        uo.x = *reinterpret_cast<unsigned*>(&h0);
        uo.y = *reinterpret_cast<unsigned*>(&h1);
        *reinterpret_cast<uint2*>(&g_o_h[row * DE + 4 * d]) = uo;
    }
}

// ---------------------------------------------------------------------------
// Launcher
// ---------------------------------------------------------------------------
extern "C" void kernel_launch(void* const* d_in, const int* in_sizes, int n_in,
                              void* d_out, int out_size) {
    const float* xq   = (const float*)d_in[0];
    const float* W_se = (const float*)d_in[2];
    const float* b_se = (const float*)d_in[3];
    const float* W_po = (const float*)d_in[4];
    const float* b_po = (const float*)d_in[5];
    const float* W_ag = (const float*)d_in[6];
    const float* b_ag = (const float*)d_in[7];
    float* out = (float*)d_out;

    __half* shh_ptr = nullptr;
    __half* oh_ptr  = nullptr;
    __half* xqh_ptr = nullptr;
    __half* w1_ptr  = nullptr;
    __half* w3_ptr  = nullptr;
    float*  b1_ptr  = nullptr;
    cudaGetSymbolAddress((void**)&shh_ptr, g_sh_h);
    cudaGetSymbolAddress((void**)&oh_ptr,  g_o_h);
    cudaGetSymbolAddress((void**)&xqh_ptr, g_xq_h);
    cudaGetSymbolAddress((void**)&w1_ptr,  g_w1_h);
    cudaGetSymbolAddress((void**)&w3_ptr,  g_w3_h);
    cudaGetSymbolAddress((void**)&b1_ptr,  g_b1);

    // fp16 conversions + channel permutation (one launch)
    conv_all_kernel<<<(TOT * DIMV) / 1024, 256>>>(xq, W_se, W_po, W_ag, b_se, b_po);

    // GEMM1+2 fused: gate | combined-gelu (fp16, permuted), + chunk sums
    {
        dim3 grid(TOT / BM, 1024 / 128);   // (128, 8)
        gemm_f16_kernel<128, 2, __half><<<grid, 256>>>(
            xqh_ptr, DIMV,
            w1_ptr, b1_ptr,
            /*op0=*/1, /*op1=*/2, /*opSplit=*/DE, /*K=*/DIMV,
            shh_ptr, /*ldo=*/1024);
    }

    scan_part_kernel<<<(BB * DE * 32) / 256, 256>>>();   // 256 blocks, warp/(b,p)
    scan_apply_kernel<<<BB * NCHUNK, 256>>>();

    // GEMM3: [16384,512] x [128,512]^T -> out (fp32); W_ag K-dim permuted
    {
        dim3 grid(TOT / BM, DIMV / 64);    // (128, 2)
        gemm_f16_kernel<64, 3, float><<<grid, 256>>>(
            oh_ptr, DE,
            w3_ptr, b_ag,
            /*op0=*/0, /*op1=*/0, /*opSplit=*/1 << 30, /*K=*/DE,
            out, /*ldo=*/DIMV);
    }
}